// round 2
// baseline (speedup 1.0000x reference)
#include <cuda_runtime.h>
#include <math.h>
#include <stdint.h>

// Problem constants
// B=64, T_IN=12, HORIZON=12, N=512, H=64, TD=32, ED=16, CHEB_K=3, D_HEADS=8
// M = B*HORIZON = 768, BN pairs = B*N = 32768

// ---------------- device scratch (allocation-free) ----------------
__device__ float g_A[512*512];                       // adjacency (row softmax)
__device__ float g_pq[768*64];                       // STE_Q @ Wq_top + bq
__device__ float g_pk[64*64];                        // STE_P @ Wk_top + bk
__device__ float g_pv[64*64];                        // STE_P @ Wv_top + bv
__device__ float g_qkvu[(size_t)32768*256];          // per (b,n): [qx|k|v|u]
__device__ float g_de[(size_t)768*512*64];           // de_input
__device__ float g_y1[(size_t)768*512*64];           // A @ y0
__device__ float g_y2[(size_t)768*512*64];           // 2A@y1 - y0
__device__ float g_yz[(size_t)768*512*64];           // z * de_input
__device__ float g_hc[(size_t)768*512*64];           // tanh gcn2
__device__ float g_zr[(size_t)768*512*128];          // sigmoid gcn1
__device__ float g_W1[(size_t)768*3*65*128];         // per-batch gcn1 weights
__device__ float g_b1[768*128];
__device__ float g_Wu[(size_t)768*3*65*64];          // per-batch gcn2 weights
__device__ float g_bu[768*64];

__device__ __forceinline__ float* buf_sel(int id){
  return id==0 ? g_de : id==1 ? g_y1 : id==2 ? g_y2 : g_yz;
}
__device__ __forceinline__ float* wbuf_sel(int id){
  return id==0 ? g_W1 : id==1 ? g_Wu : id==2 ? g_b1 : g_bu;
}

// ---------------- 1) adjacency: A = softmax(relu(E E^T), axis=1) ----------------
__global__ void k_adj(const float* __restrict__ E){
  int i = blockIdx.x;         // row
  int j = threadIdx.x;        // col (512 threads)
  __shared__ float Ei[16];
  __shared__ float red[512];
  if (j < 16) Ei[j] = E[i*16 + j];
  __syncthreads();
  float d = 0.f;
  #pragma unroll
  for (int c = 0; c < 16; c++) d = fmaf(Ei[c], E[j*16 + c], d);
  d = fmaxf(d, 0.f);
  red[j] = d; __syncthreads();
  for (int s = 256; s > 0; s >>= 1){ if (j < s) red[j] = fmaxf(red[j], red[j+s]); __syncthreads(); }
  float mx = red[0];
  __syncthreads();
  float e = __expf(d - mx);
  red[j] = e; __syncthreads();
  for (int s = 256; s > 0; s >>= 1){ if (j < s) red[j] += red[j+s]; __syncthreads(); }
  g_A[i*512 + j] = e * (1.f / red[0]);
}

// ---------------- 2) STE projections (tiny) ----------------
__global__ void k_prep(const float* __restrict__ ne1, const float* __restrict__ ne2,
                       const float* __restrict__ Wq, const float* __restrict__ bq,
                       const float* __restrict__ Wk, const float* __restrict__ bk,
                       const float* __restrict__ Wv, const float* __restrict__ bv){
  int row = blockIdx.x;
  int o = threadIdx.x;   // 64 threads
  if (row < 768){
    const float* e = ne2 + row*32;
    float a = bq[o];
    #pragma unroll
    for (int d = 0; d < 32; d++) a = fmaf(e[d], Wq[d*64 + o], a);
    g_pq[row*64 + o] = a;
  } else if (row < 832){
    int b = row - 768;
    const float* e = ne1 + (b*12 + 11)*32;   // STE_P = node_embedding1[:, -1, :]
    float a = bk[o];
    #pragma unroll
    for (int d = 0; d < 32; d++) a = fmaf(e[d], Wk[d*64 + o], a);
    g_pk[b*64 + o] = a;
  } else {
    int b = row - 832;
    const float* e = ne1 + (b*12 + 11)*32;
    float a = bv[o];
    #pragma unroll
    for (int d = 0; d < 32; d++) a = fmaf(e[d], Wv[d*64 + o], a);
    g_pv[b*64 + o] = a;
  }
}

// ---------------- 3) qx/k/v/u GEMM: (32768 x 64) @ (64 x 64) x4 matrices ----------------
// blockIdx.x = which matrix (0:qx 1:k 2:v 3:u), blockIdx.y = 64-row tile
__global__ void k_qkvu(const float* __restrict__ X, const float* __restrict__ Wq,
                       const float* __restrict__ Wk, const float* __restrict__ Wv,
                       const float* __restrict__ taw, const float* __restrict__ tab){
  int mode = blockIdx.x;
  int row0 = blockIdx.y * 64;
  const float* Wsrc = (mode==0) ? Wq + 2048 : (mode==1) ? Wk + 2048
                    : (mode==2) ? Wv + 2048 : taw;   // X-part rows 32..95 of W*, or ta_w[0]
  __shared__ float As[64][65];
  __shared__ float Bs[64][65];
  int tid = threadIdx.x;
  #pragma unroll
  for (int i = 0; i < 4; i++){
    int idx = tid + i*256;
    int r = idx >> 4, kq = idx & 15;
    float4 a4 = *(const float4*)(X + (size_t)(row0 + r)*64 + kq*4);
    As[r][kq*4+0]=a4.x; As[r][kq*4+1]=a4.y; As[r][kq*4+2]=a4.z; As[r][kq*4+3]=a4.w;
    float4 w4 = *(const float4*)(Wsrc + (size_t)r*64 + kq*4);
    Bs[r][kq*4+0]=w4.x; Bs[r][kq*4+1]=w4.y; Bs[r][kq*4+2]=w4.z; Bs[r][kq*4+3]=w4.w;
  }
  __syncthreads();
  int ty = tid >> 4, tx = tid & 15;
  float acc[4][4];
  #pragma unroll
  for (int i=0;i<4;i++){ acc[i][0]=0.f; acc[i][1]=0.f; acc[i][2]=0.f; acc[i][3]=0.f; }
  #pragma unroll 16
  for (int k = 0; k < 64; k++){
    float a[4], b[4];
    #pragma unroll
    for (int i=0;i<4;i++) a[i] = As[ty*4+i][k];
    #pragma unroll
    for (int j=0;j<4;j++) b[j] = Bs[k][tx*4+j];
    #pragma unroll
    for (int i=0;i<4;i++)
      #pragma unroll
      for (int j=0;j<4;j++) acc[i][j] = fmaf(a[i], b[j], acc[i][j]);
  }
  #pragma unroll
  for (int i=0;i<4;i++){
    int r = row0 + ty*4 + i;
    int bb = r >> 9;
    #pragma unroll
    for (int j=0;j<4;j++){
      int c = tx*4 + j;
      float v = acc[i][j];
      if (mode == 1)      v = fmaxf(v + g_pk[bb*64 + c], 0.f);
      else if (mode == 2) v = fmaxf(v + g_pv[bb*64 + c], 0.f);
      else if (mode == 3) v = v + tab[c];
      g_qkvu[(size_t)r*256 + mode*64 + c] = v;
    }
  }
}

// ---------------- 4) fused attention + output projection -> de_input ----------------
// warp per (b,n). de[b,t,n,:] = u + sum_d attn[d,t] * (v_head_d @ ta_w1_rows_d)
__global__ void k_attn2(const float* __restrict__ taw){
  const float* taw1 = taw + 4096;
  __shared__ float tw[64][64];
  __shared__ float qs[8][64], ks[8][64], vs[8][64];
  __shared__ float es[8][8][12];
  for (int i = threadIdx.x; i < 4096; i += 256) tw[i>>6][i&63] = taw1[i];
  __syncthreads();
  int w = threadIdx.x >> 5;
  int lane = threadIdx.x & 31;
  int bn = blockIdx.x*8 + w;
  int b = bn >> 9, n = bn & 511;
  const float* base = g_qkvu + (size_t)bn*256;
  int c0 = lane*2, c1 = c0 + 1;
  float qx0 = base[c0],     qx1 = base[c1];
  float kk0 = base[64+c0],  kk1 = base[64+c1];
  float vv0 = base[128+c0], vv1 = base[128+c1];
  float u0  = base[192+c0], u1  = base[192+c1];
  qs[w][c0]=qx0; qs[w][c1]=qx1;
  ks[w][c0]=kk0; ks[w][c1]=kk1;
  vs[w][c0]=vv0; vs[w][c1]=vv1;
  __syncwarp();
  // vw[d][c] = sum_{cp<8} v[d*8+cp] * ta_w1[d*8+cp][c]
  float vw0[8], vw1[8];
  #pragma unroll
  for (int d = 0; d < 8; d++){
    float a0 = 0.f, a1 = 0.f;
    #pragma unroll
    for (int cp = 0; cp < 8; cp++){
      float vv = vs[w][d*8+cp];
      float2 t2 = *(const float2*)&tw[d*8+cp][c0];
      a0 = fmaf(vv, t2.x, a0); a1 = fmaf(vv, t2.y, a1);
    }
    vw0[d] = a0; vw1[d] = a1;
  }
  // logits e[d][t] = sum_cp relu(qx + pq)[d*8+cp] * k[d*8+cp]
  for (int task = lane; task < 96; task += 32){
    int d = task / 12, t = task - d*12;
    const float* pq = g_pq + (size_t)(b*12 + t)*64 + d*8;
    float e = 0.f;
    #pragma unroll
    for (int cp = 0; cp < 8; cp++){
      float q = fmaxf(qs[w][d*8+cp] + pq[cp], 0.f);
      e = fmaf(q, ks[w][d*8+cp], e);
    }
    es[w][d][t] = e;
  }
  __syncwarp();
  if (lane < 8){  // softmax over t per head
    float mx = -1e30f;
    #pragma unroll
    for (int t=0;t<12;t++) mx = fmaxf(mx, es[w][lane][t]);
    float ssum = 0.f;
    #pragma unroll
    for (int t=0;t<12;t++){ float ex = __expf(es[w][lane][t]-mx); es[w][lane][t]=ex; ssum+=ex; }
    float inv = 1.f/ssum;
    #pragma unroll
    for (int t=0;t<12;t++) es[w][lane][t] *= inv;
  }
  __syncwarp();
  #pragma unroll
  for (int t = 0; t < 12; t++){
    float o0 = u0, o1 = u1;
    #pragma unroll
    for (int d = 0; d < 8; d++){
      float a = es[w][d][t];
      o0 = fmaf(a, vw0[d], o0); o1 = fmaf(a, vw1[d], o1);
    }
    size_t off = ((size_t)(b*12 + t)*512 + n)*64;
    *(float2*)(g_de + off + c0) = make_float2(o0, o1);
  }
}

// ---------------- 5) per-batch weight gen: C(768 x Nc) = ne2(768x32) @ Bw(32xNc) + g ----------------
__global__ void k_wgen(const float* __restrict__ Am, const float* __restrict__ Bw,
                       const float* __restrict__ g, int Nc, int dst){
  float* C = wbuf_sel(dst);
  int col0 = blockIdx.x * 64, row0 = blockIdx.y * 64;
  __shared__ float As[64][33];
  __shared__ float Bs[32][65];
  int tid = threadIdx.x;
  #pragma unroll
  for (int i = 0; i < 2; i++){
    int idx = tid + i*256;
    { int r = idx >> 3, kq = idx & 7;
      float4 a4 = *(const float4*)(Am + (size_t)(row0 + r)*32 + kq*4);
      As[r][kq*4+0]=a4.x; As[r][kq*4+1]=a4.y; As[r][kq*4+2]=a4.z; As[r][kq*4+3]=a4.w; }
    { int r = idx >> 4, cq = idx & 15;
      float4 b4 = *(const float4*)(Bw + (size_t)r*Nc + col0 + cq*4);
      Bs[r][cq*4+0]=b4.x; Bs[r][cq*4+1]=b4.y; Bs[r][cq*4+2]=b4.z; Bs[r][cq*4+3]=b4.w; }
  }
  __syncthreads();
  int ty = tid >> 4, tx = tid & 15;
  float acc[4][4];
  #pragma unroll
  for (int i=0;i<4;i++){ acc[i][0]=0.f; acc[i][1]=0.f; acc[i][2]=0.f; acc[i][3]=0.f; }
  #pragma unroll
  for (int k = 0; k < 32; k++){
    float a[4], b[4];
    #pragma unroll
    for (int i=0;i<4;i++) a[i] = As[ty*4+i][k];
    #pragma unroll
    for (int j=0;j<4;j++) b[j] = Bs[k][tx*4+j];
    #pragma unroll
    for (int i=0;i<4;i++)
      #pragma unroll
      for (int j=0;j<4;j++) acc[i][j] = fmaf(a[i], b[j], acc[i][j]);
  }
  #pragma unroll
  for (int i=0;i<4;i++){
    int r = row0 + ty*4 + i;
    #pragma unroll
    for (int j=0;j<4;j++){
      int c = col0 + tx*4 + j;
      C[(size_t)r*Nc + c] = acc[i][j] + g[c];
    }
  }
}

// ---------------- 6) batched adjacency GEMM: Out[b] = A @ X[b] (opt: 2*... - Z[b]) ----------------
// 128 threads, BM=128, BN=64 (full), BK=16, 8x8 microtile
__global__ void k_agemm(int src_id, int dst_id, int sub_id){
  const float* __restrict__ Xin = buf_sel(src_id);
  float* __restrict__ Out = buf_sel(dst_id);
  const float* Zs = (sub_id >= 0) ? buf_sel(sub_id) : nullptr;
  int bt = blockIdx.y;
  int row0 = blockIdx.x * 128;
  const float* Xb = Xin + (size_t)bt*512*64;
  __shared__ float As[128][17];
  __shared__ __align__(16) float Bs[16][64];
  int tid = threadIdx.x;
  int tx = tid & 7, ty = tid >> 3;
  float acc[8][8];
  #pragma unroll
  for (int i=0;i<8;i++)
    #pragma unroll
    for (int j=0;j<8;j++) acc[i][j] = 0.f;
  for (int k0 = 0; k0 < 512; k0 += 16){
    #pragma unroll
    for (int i = 0; i < 4; i++){
      int idx = tid + i*128;
      int r = idx >> 2, kq = idx & 3;
      float4 a4 = *(const float4*)(g_A + (size_t)(row0 + r)*512 + k0 + kq*4);
      As[r][kq*4+0]=a4.x; As[r][kq*4+1]=a4.y; As[r][kq*4+2]=a4.z; As[r][kq*4+3]=a4.w;
    }
    #pragma unroll
    for (int i = 0; i < 2; i++){
      int idx = tid + i*128;
      int r = idx >> 4, cq = idx & 15;
      float4 b4 = *(const float4*)(Xb + (size_t)(k0 + r)*64 + cq*4);
      *(float4*)&Bs[r][cq*4] = b4;
    }
    __syncthreads();
    #pragma unroll
    for (int k = 0; k < 16; k++){
      float a[8], b[8];
      #pragma unroll
      for (int i=0;i<8;i++) a[i] = As[ty*8+i][k];
      float4 b0 = *(const float4*)&Bs[k][tx*8];
      float4 b1 = *(const float4*)&Bs[k][tx*8+4];
      b[0]=b0.x; b[1]=b0.y; b[2]=b0.z; b[3]=b0.w;
      b[4]=b1.x; b[5]=b1.y; b[6]=b1.z; b[7]=b1.w;
      #pragma unroll
      for (int i=0;i<8;i++)
        #pragma unroll
        for (int j=0;j<8;j++) acc[i][j] = fmaf(a[i], b[j], acc[i][j]);
    }
    __syncthreads();
  }
  float* Ob = Out + (size_t)bt*512*64;
  const float* Zb = Zs ? Zs + (size_t)bt*512*64 : nullptr;
  #pragma unroll
  for (int i=0;i<8;i++){
    size_t r = row0 + ty*8 + i;
    #pragma unroll
    for (int j=0;j<8;j++){
      float v = acc[i][j];
      if (Zb) v = 2.f*v - Zb[r*64 + tx*8 + j];
      Ob[r*64 + tx*8 + j] = v;
    }
  }
}

// ---------------- 7) combine GEMM: act( [Y0|Y1|Y2](512x192) @ Wsel[b](192xNo) + bias[b] ) ----------------
template<int WHICH>   // 0: gcn1 -> sigmoid, zr (No=128) ; 1: gcn2 -> tanh, hc (No=64)
__global__ void k_comb(){
  constexpr int No = WHICH ? 64 : 128;
  const float* Y0   = WHICH ? g_yz : g_de;
  const float* W    = WHICH ? g_Wu : g_W1;
  const float* bias = WHICH ? g_bu : g_b1;
  float* Out        = WHICH ? g_hc : g_zr;
  int bt = blockIdx.z;
  int row0 = blockIdx.y * 64, col0 = blockIdx.x * 64;
  __shared__ float As[64][33];
  __shared__ float Bs[32][65];
  int tid = threadIdx.x, ty = tid >> 4, tx = tid & 15;
  float acc[4][4];
  #pragma unroll
  for (int i=0;i<4;i++){ acc[i][0]=0.f; acc[i][1]=0.f; acc[i][2]=0.f; acc[i][3]=0.f; }
  for (int k0 = 0; k0 < 192; k0 += 32){
    int seg = k0 >> 6, kin0 = k0 & 63;
    const float* Yb = (seg==0 ? Y0 : seg==1 ? g_y1 : g_y2) + (size_t)bt*512*64;
    #pragma unroll
    for (int i = 0; i < 2; i++){
      int idx = tid + i*256;
      int r = idx >> 3, kq = idx & 7;
      float4 a4 = *(const float4*)(Yb + (size_t)(row0 + r)*64 + kin0 + kq*4);
      As[r][kq*4+0]=a4.x; As[r][kq*4+1]=a4.y; As[r][kq*4+2]=a4.z; As[r][kq*4+3]=a4.w;
    }
    // weight rows i = kin0+r+1 (channel 0 of gcn input is identically zero)
    const float* Wb = W + ((size_t)bt*3 + seg)*65*No + (size_t)(kin0 + 1)*No + col0;
    #pragma unroll
    for (int i = 0; i < 2; i++){
      int idx = tid + i*256;
      int r = idx >> 4, cq = idx & 15;
      float4 w4 = *(const float4*)(Wb + (size_t)r*No + cq*4);
      Bs[r][cq*4+0]=w4.x; Bs[r][cq*4+1]=w4.y; Bs[r][cq*4+2]=w4.z; Bs[r][cq*4+3]=w4.w;
    }
    __syncthreads();
    #pragma unroll
    for (int k = 0; k < 32; k++){
      float a[4], b[4];
      #pragma unroll
      for (int i=0;i<4;i++) a[i] = As[ty*4+i][k];
      #pragma unroll
      for (int j=0;j<4;j++) b[j] = Bs[k][tx*4+j];
      #pragma unroll
      for (int i=0;i<4;i++)
        #pragma unroll
        for (int j=0;j<4;j++) acc[i][j] = fmaf(a[i], b[j], acc[i][j]);
    }
    __syncthreads();
  }
  float* Ob = Out + ((size_t)bt*512 + row0)*No + col0;
  #pragma unroll
  for (int i=0;i<4;i++){
    #pragma unroll
    for (int j=0;j<4;j++){
      float v = acc[i][j] + bias[bt*No + col0 + tx*4 + j];
      v = WHICH ? tanhf(v) : 1.f/(1.f + __expf(-v));
      Ob[(size_t)(ty*4+i)*No + tx*4 + j] = v;
    }
  }
}

// ---------------- 8) yz = z * de ----------------
__global__ void k_zde(){
  size_t idx = (size_t)blockIdx.x * blockDim.x + threadIdx.x;
  if (idx >= (size_t)768*512*64) return;
  size_t mn = idx >> 6;
  int h = (int)(idx & 63);
  g_yz[idx] = g_zr[(mn << 7) + h] * g_de[idx];
}

// ---------------- 9) final: out[m,n] = sum_h (rg*de + (1-rg)*hc) * out_w[t,h] + out_b[t] ----------------
__global__ void k_out(const float* __restrict__ outw, const float* __restrict__ outb,
                      float* __restrict__ out){
  int gw = blockIdx.x*8 + (threadIdx.x >> 5);
  int lane = threadIdx.x & 31;
  size_t mn = (size_t)gw;
  int m = gw >> 9;
  int t = m % 12;
  size_t base = mn << 6;
  float s = 0.f;
  #pragma unroll
  for (int ii = 0; ii < 2; ii++){
    int i = lane + ii*32;
    float rg = g_zr[(mn << 7) + 64 + i];
    float de = g_de[base + i];
    float hc = g_hc[base + i];
    float st = fmaf(rg, de - hc, hc);     // rg*de + (1-rg)*hc
    s = fmaf(st, outw[t*64 + i], s);
  }
  #pragma unroll
  for (int off = 16; off > 0; off >>= 1) s += __shfl_xor_sync(0xffffffffu, s, off);
  if (lane == 0) out[mn] = s + outb[t];
}

// ---------------- launch ----------------
extern "C" void kernel_launch(void* const* d_in, const int* in_sizes, int n_in,
                              void* d_out, int out_size){
  (void)in_sizes; (void)n_in; (void)out_size;
  const float* hn  = (const float*)d_in[2];   // h_n (1,B,N,H)
  const float* ne1 = (const float*)d_in[3];
  const float* ne2 = (const float*)d_in[4];
  const float* E   = (const float*)d_in[5];
  const float* Wq  = (const float*)d_in[6];
  const float* bq  = (const float*)d_in[7];
  const float* Wk  = (const float*)d_in[8];
  const float* bk  = (const float*)d_in[9];
  const float* Wv  = (const float*)d_in[10];
  const float* bv  = (const float*)d_in[11];
  const float* taw = (const float*)d_in[12];
  const float* tab = (const float*)d_in[13];
  const float* gwp = (const float*)d_in[14];
  const float* gw  = (const float*)d_in[15];
  const float* gbp = (const float*)d_in[16];
  const float* gb  = (const float*)d_in[17];
  const float* uwp = (const float*)d_in[18];
  const float* uw  = (const float*)d_in[19];
  const float* ubp = (const float*)d_in[20];
  const float* ub  = (const float*)d_in[21];
  const float* outw= (const float*)d_in[22];
  const float* outb= (const float*)d_in[23];
  float* out = (float*)d_out;

  k_adj<<<512, 512>>>(E);
  k_prep<<<896, 64>>>(ne1, ne2, Wq, bq, Wk, bk, Wv, bv);
  k_qkvu<<<dim3(4, 512), 256>>>(hn, Wq, Wk, Wv, taw, tab);
  k_attn2<<<4096, 256>>>(taw);
  k_wgen<<<dim3(390, 12), 256>>>(ne2, gwp, gw, 24960, 0);
  k_wgen<<<dim3(195, 12), 256>>>(ne2, uwp, uw, 12480, 1);
  k_wgen<<<dim3(2, 12), 256>>>(ne2, gbp, gb, 128, 2);
  k_wgen<<<dim3(1, 12), 256>>>(ne2, ubp, ub, 64, 3);
  k_agemm<<<dim3(4, 768), 128>>>(0, 1, -1);   // y1 = A @ de
  k_agemm<<<dim3(4, 768), 128>>>(1, 2, 0);    // y2 = 2A@y1 - de
  k_comb<0><<<dim3(2, 8, 768), 256>>>();      // zr = sigmoid(...)
  k_zde<<<98304, 256>>>();                    // yz = z * de
  k_agemm<<<dim3(4, 768), 128>>>(3, 1, -1);   // y1 = A @ yz
  k_agemm<<<dim3(4, 768), 128>>>(1, 2, 3);    // y2 = 2A@y1 - yz
  k_comb<1><<<dim3(1, 8, 768), 256>>>();      // hc = tanh(...)
  k_out<<<49152, 256>>>(outw, outb, out);
}

// round 4
// speedup vs baseline: 1.4949x; 1.4949x over previous
#include <cuda_runtime.h>
#include <cuda_bf16.h>
#include <math.h>
#include <stdint.h>

// B=64, T=12, N=512, H=64, TD=32, ED=16, CHEB_K=3, D_HEADS=8, M=768
constexpr size_t NF = (size_t)768*512*64;

// ---------------- device scratch ----------------
__device__ __nv_bfloat16 g_Ah[512*512], g_Al[512*512];
__device__ float g_pq[768*64], g_pk[64*64], g_pv[64*64];
__device__ float g_qkvu[(size_t)32768*256];
__device__ float g_de[NF], g_y1[NF], g_y2[NF], g_yz[NF], g_hc[NF];
__device__ __nv_bfloat16 g_deh[NF], g_del[NF], g_y1h[NF], g_y1l[NF], g_yzh[NF], g_yzl[NF];
__device__ float g_zr[(size_t)768*512*128];
__device__ float g_W1[(size_t)768*3*65*128], g_b1[768*128];
__device__ float g_Wu[(size_t)768*3*65*64],  g_bu[768*64];

__device__ __forceinline__ float* wbuf_sel(int id){
  return id==0 ? g_W1 : id==1 ? g_Wu : id==2 ? g_b1 : g_bu;
}

// ---------------- ptx helpers (all sm_80+ baseline, no "a"-gated features) ----------------
__device__ __forceinline__ uint32_t s2u(const void* p){
  uint32_t a;
  asm("{ .reg .u64 t; cvta.to.shared.u64 t, %1; cvt.u32.u64 %0, t; }" : "=r"(a) : "l"(p));
  return a;
}
__device__ __forceinline__ void cp16(uint32_t dst, const void* src){
  asm volatile("cp.async.cg.shared.global [%0], [%1], 16;" :: "r"(dst), "l"(src) : "memory");
}
__device__ __forceinline__ void ldm_x4(uint32_t* r, uint32_t addr){
  asm volatile("ldmatrix.sync.aligned.m8n8.x4.shared.b16 {%0,%1,%2,%3}, [%4];"
    : "=r"(r[0]), "=r"(r[1]), "=r"(r[2]), "=r"(r[3]) : "r"(addr));
}
__device__ __forceinline__ void ldm_x4t(uint32_t* r, uint32_t addr){
  asm volatile("ldmatrix.sync.aligned.m8n8.x4.trans.shared.b16 {%0,%1,%2,%3}, [%4];"
    : "=r"(r[0]), "=r"(r[1]), "=r"(r[2]), "=r"(r[3]) : "r"(addr));
}
__device__ __forceinline__ void mma_bf16(float* c, const uint32_t* a, uint32_t b0, uint32_t b1){
  asm volatile(
    "mma.sync.aligned.m16n8k16.row.col.f32.bf16.bf16.f32 "
    "{%0,%1,%2,%3}, {%4,%5,%6,%7}, {%8,%9}, {%0,%1,%2,%3};"
    : "+f"(c[0]), "+f"(c[1]), "+f"(c[2]), "+f"(c[3])
    : "r"(a[0]), "r"(a[1]), "r"(a[2]), "r"(a[3]), "r"(b0), "r"(b1));
}
__device__ __forceinline__ void split_bf16(float f, __nv_bfloat16& h, __nv_bfloat16& l){
  h = __float2bfloat16(f);
  l = __float2bfloat16(f - __bfloat162float(h));
}

// ---------------- 1) adjacency: A = softmax(relu(E E^T)), emit bf16 hi/lo ----------------
__global__ void k_adj(const float* __restrict__ E){
  int i = blockIdx.x, j = threadIdx.x;
  __shared__ float Ei[16];
  __shared__ float red[512];
  if (j < 16) Ei[j] = E[i*16 + j];
  __syncthreads();
  float d = 0.f;
  #pragma unroll
  for (int c = 0; c < 16; c++) d = fmaf(Ei[c], E[j*16 + c], d);
  d = fmaxf(d, 0.f);
  red[j] = d; __syncthreads();
  for (int s = 256; s > 0; s >>= 1){ if (j < s) red[j] = fmaxf(red[j], red[j+s]); __syncthreads(); }
  float mx = red[0];
  __syncthreads();
  float e = __expf(d - mx);
  red[j] = e; __syncthreads();
  for (int s = 256; s > 0; s >>= 1){ if (j < s) red[j] += red[j+s]; __syncthreads(); }
  float a = e * (1.f / red[0]);
  __nv_bfloat16 h, l; split_bf16(a, h, l);
  g_Ah[i*512 + j] = h; g_Al[i*512 + j] = l;
}

// ---------------- 2) STE projections ----------------
__global__ void k_prep(const float* __restrict__ ne1, const float* __restrict__ ne2,
                       const float* __restrict__ Wq, const float* __restrict__ bq,
                       const float* __restrict__ Wk, const float* __restrict__ bk,
                       const float* __restrict__ Wv, const float* __restrict__ bv){
  int row = blockIdx.x, o = threadIdx.x;
  if (row < 768){
    const float* e = ne2 + row*32;
    float a = bq[o];
    #pragma unroll
    for (int d = 0; d < 32; d++) a = fmaf(e[d], Wq[d*64 + o], a);
    g_pq[row*64 + o] = a;
  } else if (row < 832){
    int b = row - 768;
    const float* e = ne1 + (b*12 + 11)*32;
    float a = bk[o];
    #pragma unroll
    for (int d = 0; d < 32; d++) a = fmaf(e[d], Wk[d*64 + o], a);
    g_pk[b*64 + o] = a;
  } else {
    int b = row - 832;
    const float* e = ne1 + (b*12 + 11)*32;
    float a = bv[o];
    #pragma unroll
    for (int d = 0; d < 32; d++) a = fmaf(e[d], Wv[d*64 + o], a);
    g_pv[b*64 + o] = a;
  }
}

// ---------------- 3) qkvu GEMM ----------------
__global__ void k_qkvu(const float* __restrict__ X, const float* __restrict__ Wq,
                       const float* __restrict__ Wk, const float* __restrict__ Wv,
                       const float* __restrict__ taw, const float* __restrict__ tab){
  int mode = blockIdx.x;
  int row0 = blockIdx.y * 64;
  const float* Wsrc = (mode==0) ? Wq + 2048 : (mode==1) ? Wk + 2048
                    : (mode==2) ? Wv + 2048 : taw;
  __shared__ float As[64][65];
  __shared__ float Bs[64][65];
  int tid = threadIdx.x;
  #pragma unroll
  for (int i = 0; i < 4; i++){
    int idx = tid + i*256;
    int r = idx >> 4, kq = idx & 15;
    float4 a4 = *(const float4*)(X + (size_t)(row0 + r)*64 + kq*4);
    As[r][kq*4+0]=a4.x; As[r][kq*4+1]=a4.y; As[r][kq*4+2]=a4.z; As[r][kq*4+3]=a4.w;
    float4 w4 = *(const float4*)(Wsrc + (size_t)r*64 + kq*4);
    Bs[r][kq*4+0]=w4.x; Bs[r][kq*4+1]=w4.y; Bs[r][kq*4+2]=w4.z; Bs[r][kq*4+3]=w4.w;
  }
  __syncthreads();
  int ty = tid >> 4, tx = tid & 15;
  float acc[4][4];
  #pragma unroll
  for (int i=0;i<4;i++){ acc[i][0]=0.f; acc[i][1]=0.f; acc[i][2]=0.f; acc[i][3]=0.f; }
  #pragma unroll 16
  for (int k = 0; k < 64; k++){
    float a[4], b[4];
    #pragma unroll
    for (int i=0;i<4;i++) a[i] = As[ty*4+i][k];
    #pragma unroll
    for (int j=0;j<4;j++) b[j] = Bs[k][tx*4+j];
    #pragma unroll
    for (int i=0;i<4;i++)
      #pragma unroll
      for (int j=0;j<4;j++) acc[i][j] = fmaf(a[i], b[j], acc[i][j]);
  }
  #pragma unroll
  for (int i=0;i<4;i++){
    int r = row0 + ty*4 + i;
    int bb = r >> 9;
    #pragma unroll
    for (int j=0;j<4;j++){
      int c = tx*4 + j;
      float v = acc[i][j];
      if (mode == 1)      v = fmaxf(v + g_pk[bb*64 + c], 0.f);
      else if (mode == 2) v = fmaxf(v + g_pv[bb*64 + c], 0.f);
      else if (mode == 3) v = v + tab[c];
      g_qkvu[(size_t)r*256 + mode*64 + c] = v;
    }
  }
}

// ---------------- 4) fused attention -> de (fp32 + bf16 hi/lo) ----------------
__global__ void k_attn2(const float* __restrict__ taw){
  const float* taw1 = taw + 4096;
  __shared__ float tw[64][64];
  __shared__ float qs[8][64], ks[8][64], vs[8][64];
  __shared__ float es[8][8][12];
  for (int i = threadIdx.x; i < 4096; i += 256) tw[i>>6][i&63] = taw1[i];
  __syncthreads();
  int w = threadIdx.x >> 5;
  int lane = threadIdx.x & 31;
  int bn = blockIdx.x*8 + w;
  int b = bn >> 9, n = bn & 511;
  const float* base = g_qkvu + (size_t)bn*256;
  int c0 = lane*2, c1 = c0 + 1;
  float u0  = base[192+c0], u1  = base[192+c1];
  qs[w][c0]=base[c0];     qs[w][c1]=base[c1];
  ks[w][c0]=base[64+c0];  ks[w][c1]=base[64+c1];
  vs[w][c0]=base[128+c0]; vs[w][c1]=base[128+c1];
  __syncwarp();
  float vw0[8], vw1[8];
  #pragma unroll
  for (int d = 0; d < 8; d++){
    float a0 = 0.f, a1 = 0.f;
    #pragma unroll
    for (int cp = 0; cp < 8; cp++){
      float vv = vs[w][d*8+cp];
      float2 t2 = *(const float2*)&tw[d*8+cp][c0];
      a0 = fmaf(vv, t2.x, a0); a1 = fmaf(vv, t2.y, a1);
    }
    vw0[d] = a0; vw1[d] = a1;
  }
  for (int task = lane; task < 96; task += 32){
    int d = task / 12, t = task - d*12;
    const float* pq = g_pq + (size_t)(b*12 + t)*64 + d*8;
    float e = 0.f;
    #pragma unroll
    for (int cp = 0; cp < 8; cp++){
      float q = fmaxf(qs[w][d*8+cp] + pq[cp], 0.f);
      e = fmaf(q, ks[w][d*8+cp], e);
    }
    es[w][d][t] = e;
  }
  __syncwarp();
  if (lane < 8){
    float mx = -1e30f;
    #pragma unroll
    for (int t=0;t<12;t++) mx = fmaxf(mx, es[w][lane][t]);
    float ssum = 0.f;
    #pragma unroll
    for (int t=0;t<12;t++){ float ex = __expf(es[w][lane][t]-mx); es[w][lane][t]=ex; ssum+=ex; }
    float inv = 1.f/ssum;
    #pragma unroll
    for (int t=0;t<12;t++) es[w][lane][t] *= inv;
  }
  __syncwarp();
  #pragma unroll
  for (int t = 0; t < 12; t++){
    float o0 = u0, o1 = u1;
    #pragma unroll
    for (int d = 0; d < 8; d++){
      float a = es[w][d][t];
      o0 = fmaf(a, vw0[d], o0); o1 = fmaf(a, vw1[d], o1);
    }
    size_t off = ((size_t)(b*12 + t)*512 + n)*64;
    *(float2*)(g_de + off + c0) = make_float2(o0, o1);
    __nv_bfloat16 h0,l0,h1,l1;
    split_bf16(o0,h0,l0); split_bf16(o1,h1,l1);
    __nv_bfloat162 hv; hv.x=h0; hv.y=h1;
    __nv_bfloat162 lv; lv.x=l0; lv.y=l1;
    *(__nv_bfloat162*)(g_deh + off + c0) = hv;
    *(__nv_bfloat162*)(g_del + off + c0) = lv;
  }
}

// ---------------- 5) weight gen ----------------
__global__ void k_wgen(const float* __restrict__ Am, const float* __restrict__ Bw,
                       const float* __restrict__ g, int Nc, int dst){
  float* C = wbuf_sel(dst);
  int col0 = blockIdx.x * 64, row0 = blockIdx.y * 64;
  __shared__ float As[64][33];
  __shared__ float Bs[32][65];
  int tid = threadIdx.x;
  #pragma unroll
  for (int i = 0; i < 2; i++){
    int idx = tid + i*256;
    { int r = idx >> 3, kq = idx & 7;
      float4 a4 = *(const float4*)(Am + (size_t)(row0 + r)*32 + kq*4);
      As[r][kq*4+0]=a4.x; As[r][kq*4+1]=a4.y; As[r][kq*4+2]=a4.z; As[r][kq*4+3]=a4.w; }
    { int r = idx >> 4, cq = idx & 15;
      float4 b4 = *(const float4*)(Bw + (size_t)r*Nc + col0 + cq*4);
      Bs[r][cq*4+0]=b4.x; Bs[r][cq*4+1]=b4.y; Bs[r][cq*4+2]=b4.z; Bs[r][cq*4+3]=b4.w; }
  }
  __syncthreads();
  int ty = tid >> 4, tx = tid & 15;
  float acc[4][4];
  #pragma unroll
  for (int i=0;i<4;i++){ acc[i][0]=0.f; acc[i][1]=0.f; acc[i][2]=0.f; acc[i][3]=0.f; }
  #pragma unroll
  for (int k = 0; k < 32; k++){
    float a[4], b[4];
    #pragma unroll
    for (int i=0;i<4;i++) a[i] = As[ty*4+i][k];
    #pragma unroll
    for (int j=0;j<4;j++) b[j] = Bs[k][tx*4+j];
    #pragma unroll
    for (int i=0;i<4;i++)
      #pragma unroll
      for (int j=0;j<4;j++) acc[i][j] = fmaf(a[i], b[j], acc[i][j]);
  }
  #pragma unroll
  for (int i=0;i<4;i++){
    int r = row0 + ty*4 + i;
    #pragma unroll
    for (int j=0;j<4;j++){
      int c = col0 + tx*4 + j;
      C[(size_t)r*Nc + c] = acc[i][j] + g[c];
    }
  }
}

// ---------------- 6) HMMA batched adjacency GEMM (bf16 hi/lo 3-term) ----------------
// D(128x64) = A[m0:m0+128, :] @ X[bt] ; mode 0: y1 = D (fp32 + bf16 h/l)
//                                       mode 1: y2 = 2D - Z (fp32)
// CTA: 256 thr = 8 warps (4m x 2n), tile 128x64, BK=16, 32 chunks, cp.async 2-stage.
__global__ void __launch_bounds__(256, 2) k_bmma(int src_id, int mode, int z_id){
  const __nv_bfloat16* __restrict__ Bh = src_id==0 ? g_deh : src_id==1 ? g_y1h : g_yzh;
  const __nv_bfloat16* __restrict__ Bl = src_id==0 ? g_del : src_id==1 ? g_y1l : g_yzl;
  const float* __restrict__ Z = z_id==0 ? g_de : g_yz;

  __shared__ __nv_bfloat16 sAh[2][128*24], sAl[2][128*24];   // row stride 24 bf16 (48B)
  __shared__ __nv_bfloat16 sXh[2][16*72],  sXl[2][16*72];    // row stride 72 bf16 (144B)

  int bt = blockIdx.y, m0 = blockIdx.x * 128;
  int tid = threadIdx.x, wid = tid >> 5, lane = tid & 31;
  int warp_m = wid >> 1, warp_n = wid & 1;

  uint32_t uAh[2] = { s2u(sAh[0]), s2u(sAh[1]) };
  uint32_t uAl[2] = { s2u(sAl[0]), s2u(sAl[1]) };
  uint32_t uXh[2] = { s2u(sXh[0]), s2u(sXh[1]) };
  uint32_t uXl[2] = { s2u(sXl[0]), s2u(sXl[1]) };

  // per-thread load coords
  int arow = tid >> 1, aq = tid & 1;           // A: 128 rows x 2 x 16B per matrix
  int xr = (tid & 127) >> 3, xq = tid & 7;     // X: 16 rows x 8 x 16B per matrix
  bool xhi = tid < 128;

  auto load_chunk = [&](int c, int buf){
    int k0 = c * 16;
    size_t ga = (size_t)(m0 + arow)*512 + k0 + aq*8;
    cp16(uAh[buf] + arow*48 + aq*16, g_Ah + ga);
    cp16(uAl[buf] + arow*48 + aq*16, g_Al + ga);
    size_t gx = ((size_t)bt*512 + k0 + xr)*64 + xq*8;
    if (xhi) cp16(uXh[buf] + xr*144 + xq*16, Bh + gx);
    else     cp16(uXl[buf] + xr*144 + xq*16, Bl + gx);
  };

  float acc[2][4][4];
  #pragma unroll
  for (int mi=0;mi<2;mi++)
    #pragma unroll
    for (int nn=0;nn<4;nn++)
      #pragma unroll
      for (int j=0;j<4;j++) acc[mi][nn][j] = 0.f;

  load_chunk(0, 0);
  asm volatile("cp.async.commit_group;" ::: "memory");

  uint32_t lrow = lane & 15;
  uint32_t lk = (lane >> 4) << 4;   // 0 or 16 bytes

  for (int c = 0; c < 32; c++){
    int buf = c & 1;
    if (c < 31){
      load_chunk(c + 1, buf ^ 1);
      asm volatile("cp.async.commit_group;" ::: "memory");
      asm volatile("cp.async.wait_group 1;" ::: "memory");
    } else {
      asm volatile("cp.async.wait_group 0;" ::: "memory");
    }
    __syncthreads();

    uint32_t ah[2][4], al[2][4], bh[2][4], bl[2][4];
    #pragma unroll
    for (int mi = 0; mi < 2; mi++){
      uint32_t aoff = (uint32_t)(warp_m*32 + mi*16 + lrow)*48 + lk;
      ldm_x4(ah[mi], uAh[buf] + aoff);
      ldm_x4(al[mi], uAl[buf] + aoff);
    }
    #pragma unroll
    for (int np = 0; np < 2; np++){
      uint32_t boff = lrow*144 + (uint32_t)(warp_n*32 + np*16)*2 + lk;
      ldm_x4t(bh[np], uXh[buf] + boff);
      ldm_x4t(bl[np], uXl[buf] + boff);
    }
    #pragma unroll
    for (int mi = 0; mi < 2; mi++){
      #pragma unroll
      for (int nn = 0; nn < 4; nn++){
        int np = nn >> 1, sub = (nn & 1) * 2;
        mma_bf16(acc[mi][nn], ah[mi], bh[np][sub], bh[np][sub+1]);
        mma_bf16(acc[mi][nn], ah[mi], bl[np][sub], bl[np][sub+1]);
        mma_bf16(acc[mi][nn], al[mi], bh[np][sub], bh[np][sub+1]);
      }
    }
    __syncthreads();
  }

  // epilogue: thread holds (row t/4, col 2(t%4)) pairs, rows +0/+8
  int rbase = m0 + warp_m*32 + (lane >> 2);
  int cbase = warp_n*32 + (lane & 3)*2;
  #pragma unroll
  for (int mi = 0; mi < 2; mi++){
    #pragma unroll
    for (int nn = 0; nn < 4; nn++){
      int col = cbase + nn*8;
      #pragma unroll
      for (int half = 0; half < 2; half++){
        int row = rbase + mi*16 + half*8;
        size_t off = ((size_t)bt*512 + row)*64 + col;
        float v0 = acc[mi][nn][half*2], v1 = acc[mi][nn][half*2+1];
        if (mode == 0){
          *(float2*)(g_y1 + off) = make_float2(v0, v1);
          __nv_bfloat16 h0,l0,h1,l1;
          split_bf16(v0,h0,l0); split_bf16(v1,h1,l1);
          __nv_bfloat162 hv; hv.x=h0; hv.y=h1;
          __nv_bfloat162 lv; lv.x=l0; lv.y=l1;
          *(__nv_bfloat162*)(g_y1h + off) = hv;
          *(__nv_bfloat162*)(g_y1l + off) = lv;
        } else {
          float2 z = *(const float2*)(Z + off);
          *(float2*)(g_y2 + off) = make_float2(2.f*v0 - z.x, 2.f*v1 - z.y);
        }
      }
    }
  }
}

// ---------------- 7) combine GEMM (SIMT fp32) ----------------
template<int WHICH>
__global__ void k_comb(){
  constexpr int No = WHICH ? 64 : 128;
  const float* Y0   = WHICH ? g_yz : g_de;
  const float* W    = WHICH ? g_Wu : g_W1;
  const float* bias = WHICH ? g_bu : g_b1;
  float* Out        = WHICH ? g_hc : g_zr;
  int bt = blockIdx.z;
  int row0 = blockIdx.y * 64, col0 = blockIdx.x * 64;
  __shared__ float As[64][33];
  __shared__ float Bs[32][65];
  int tid = threadIdx.x, ty = tid >> 4, tx = tid & 15;
  float acc[4][4];
  #pragma unroll
  for (int i=0;i<4;i++){ acc[i][0]=0.f; acc[i][1]=0.f; acc[i][2]=0.f; acc[i][3]=0.f; }
  for (int k0 = 0; k0 < 192; k0 += 32){
    int seg = k0 >> 6, kin0 = k0 & 63;
    const float* Yb = (seg==0 ? Y0 : seg==1 ? g_y1 : g_y2) + (size_t)bt*512*64;
    #pragma unroll
    for (int i = 0; i < 2; i++){
      int idx = tid + i*256;
      int r = idx >> 3, kq = idx & 7;
      float4 a4 = *(const float4*)(Yb + (size_t)(row0 + r)*64 + kin0 + kq*4);
      As[r][kq*4+0]=a4.x; As[r][kq*4+1]=a4.y; As[r][kq*4+2]=a4.z; As[r][kq*4+3]=a4.w;
    }
    const float* Wb = W + ((size_t)bt*3 + seg)*65*No + (size_t)(kin0 + 1)*No + col0;
    #pragma unroll
    for (int i = 0; i < 2; i++){
      int idx = tid + i*256;
      int r = idx >> 4, cq = idx & 15;
      float4 w4 = *(const float4*)(Wb + (size_t)r*No + cq*4);
      Bs[r][cq*4+0]=w4.x; Bs[r][cq*4+1]=w4.y; Bs[r][cq*4+2]=w4.z; Bs[r][cq*4+3]=w4.w;
    }
    __syncthreads();
    #pragma unroll
    for (int k = 0; k < 32; k++){
      float a[4], b[4];
      #pragma unroll
      for (int i=0;i<4;i++) a[i] = As[ty*4+i][k];
      #pragma unroll
      for (int j=0;j<4;j++) b[j] = Bs[k][tx*4+j];
      #pragma unroll
      for (int i=0;i<4;i++)
        #pragma unroll
        for (int j=0;j<4;j++) acc[i][j] = fmaf(a[i], b[j], acc[i][j]);
    }
    __syncthreads();
  }
  float* Ob = Out + ((size_t)bt*512 + row0)*No + col0;
  #pragma unroll
  for (int i=0;i<4;i++){
    #pragma unroll
    for (int j=0;j<4;j++){
      float v = acc[i][j] + bias[bt*No + col0 + tx*4 + j];
      v = WHICH ? tanhf(v) : 1.f/(1.f + __expf(-v));
      Ob[(size_t)(ty*4+i)*No + tx*4 + j] = v;
    }
  }
}

// ---------------- 8) yz = z * de (+ bf16 hi/lo) ----------------
__global__ void k_zde(){
  size_t idx = (size_t)blockIdx.x * blockDim.x + threadIdx.x;
  if (idx >= NF) return;
  size_t mn = idx >> 6;
  int h = (int)(idx & 63);
  float v = g_zr[(mn << 7) + h] * g_de[idx];
  g_yz[idx] = v;
  __nv_bfloat16 hh, ll; split_bf16(v, hh, ll);
  g_yzh[idx] = hh; g_yzl[idx] = ll;
}

// ---------------- 9) final projection ----------------
__global__ void k_out(const float* __restrict__ outw, const float* __restrict__ outb,
                      float* __restrict__ out){
  int gw = blockIdx.x*8 + (threadIdx.x >> 5);
  int lane = threadIdx.x & 31;
  size_t mn = (size_t)gw;
  int m = gw >> 9;
  int t = m % 12;
  size_t base = mn << 6;
  float s = 0.f;
  #pragma unroll
  for (int ii = 0; ii < 2; ii++){
    int i = lane + ii*32;
    float rg = g_zr[(mn << 7) + 64 + i];
    float de = g_de[base + i];
    float hc = g_hc[base + i];
    float st = fmaf(rg, de - hc, hc);
    s = fmaf(st, outw[t*64 + i], s);
  }
  #pragma unroll
  for (int off = 16; off > 0; off >>= 1) s += __shfl_xor_sync(0xffffffffu, s, off);
  if (lane == 0) out[mn] = s + outb[t];
}

// ---------------- launch ----------------
extern "C" void kernel_launch(void* const* d_in, const int* in_sizes, int n_in,
                              void* d_out, int out_size){
  (void)in_sizes; (void)n_in; (void)out_size;
  const float* hn  = (const float*)d_in[2];
  const float* ne1 = (const float*)d_in[3];
  const float* ne2 = (const float*)d_in[4];
  const float* E   = (const float*)d_in[5];
  const float* Wq  = (const float*)d_in[6];
  const float* bq  = (const float*)d_in[7];
  const float* Wk  = (const float*)d_in[8];
  const float* bk  = (const float*)d_in[9];
  const float* Wv  = (const float*)d_in[10];
  const float* bv  = (const float*)d_in[11];
  const float* taw = (const float*)d_in[12];
  const float* tab = (const float*)d_in[13];
  const float* gwp = (const float*)d_in[14];
  const float* gw  = (const float*)d_in[15];
  const float* gbp = (const float*)d_in[16];
  const float* gb  = (const float*)d_in[17];
  const float* uwp = (const float*)d_in[18];
  const float* uw  = (const float*)d_in[19];
  const float* ubp = (const float*)d_in[20];
  const float* ub  = (const float*)d_in[21];
  const float* outw= (const float*)d_in[22];
  const float* outb= (const float*)d_in[23];
  float* out = (float*)d_out;

  k_adj<<<512, 512>>>(E);
  k_prep<<<896, 64>>>(ne1, ne2, Wq, bq, Wk, bk, Wv, bv);
  k_qkvu<<<dim3(4, 512), 256>>>(hn, Wq, Wk, Wv, taw, tab);
  k_attn2<<<4096, 256>>>(taw);
  k_wgen<<<dim3(390, 12), 256>>>(ne2, gwp, gw, 24960, 0);
  k_wgen<<<dim3(195, 12), 256>>>(ne2, uwp, uw, 12480, 1);
  k_wgen<<<dim3(2, 12), 256>>>(ne2, gbp, gb, 128, 2);
  k_wgen<<<dim3(1, 12), 256>>>(ne2, ubp, ub, 64, 3);
  k_bmma<<<dim3(4, 768), 256>>>(0, 0, 0);   // y1 = A @ de
  k_bmma<<<dim3(4, 768), 256>>>(1, 1, 0);   // y2 = 2A@y1 - de
  k_comb<0><<<dim3(2, 8, 768), 256>>>();    // zr
  k_zde<<<98304, 256>>>();                  // yz = z * de
  k_bmma<<<dim3(4, 768), 256>>>(2, 0, 0);   // y1 = A @ yz
  k_bmma<<<dim3(4, 768), 256>>>(1, 1, 2);   // y2 = 2A@y1 - yz
  k_comb<1><<<dim3(1, 8, 768), 256>>>();    // hc
  k_out<<<49152, 256>>>(outw, outb, out);
}

// round 5
// speedup vs baseline: 1.8733x; 1.2531x over previous
#include <cuda_runtime.h>
#include <cuda_bf16.h>
#include <math.h>
#include <stdint.h>

// B=64, T=12, N=512, H=64, TD=32, ED=16, CHEB_K=3, D_HEADS=8, M=768
constexpr size_t NF = (size_t)768*512*64;

// ---------------- device scratch ----------------
__device__ __nv_bfloat16 g_Ah[512*512], g_Al[512*512];
__device__ float g_pq[768*64], g_pk[64*64], g_pv[64*64];
__device__ float g_qkvu[(size_t)32768*256];
__device__ float g_de[NF], g_y1[NF], g_y2[NF], g_yz[NF], g_hc[NF], g_rg[NF];
__device__ __nv_bfloat16 g_deh[NF], g_del[NF], g_y1h[NF], g_y1l[NF];
__device__ __nv_bfloat16 g_y2h[NF], g_y2l[NF], g_yzh[NF], g_yzl[NF];
__device__ __nv_bfloat16 g_W1h[(size_t)768*3*64*128], g_W1l[(size_t)768*3*64*128];
__device__ __nv_bfloat16 g_Wuh[(size_t)768*3*64*64],  g_Wul[(size_t)768*3*64*64];
__device__ float g_b1[768*128], g_bu[768*64];

// ---------------- ptx helpers (sm_80+ baseline only) ----------------
__device__ __forceinline__ uint32_t s2u(const void* p){
  uint32_t a;
  asm("{ .reg .u64 t; cvta.to.shared.u64 t, %1; cvt.u32.u64 %0, t; }" : "=r"(a) : "l"(p));
  return a;
}
__device__ __forceinline__ void cp16(uint32_t dst, const void* src){
  asm volatile("cp.async.cg.shared.global [%0], [%1], 16;" :: "r"(dst), "l"(src) : "memory");
}
__device__ __forceinline__ void ldm_x4(uint32_t* r, uint32_t addr){
  asm volatile("ldmatrix.sync.aligned.m8n8.x4.shared.b16 {%0,%1,%2,%3}, [%4];"
    : "=r"(r[0]), "=r"(r[1]), "=r"(r[2]), "=r"(r[3]) : "r"(addr));
}
__device__ __forceinline__ void ldm_x4t(uint32_t* r, uint32_t addr){
  asm volatile("ldmatrix.sync.aligned.m8n8.x4.trans.shared.b16 {%0,%1,%2,%3}, [%4];"
    : "=r"(r[0]), "=r"(r[1]), "=r"(r[2]), "=r"(r[3]) : "r"(addr));
}
__device__ __forceinline__ void mma_bf16(float* c, const uint32_t* a, uint32_t b0, uint32_t b1){
  asm volatile(
    "mma.sync.aligned.m16n8k16.row.col.f32.bf16.bf16.f32 "
    "{%0,%1,%2,%3}, {%4,%5,%6,%7}, {%8,%9}, {%0,%1,%2,%3};"
    : "+f"(c[0]), "+f"(c[1]), "+f"(c[2]), "+f"(c[3])
    : "r"(a[0]), "r"(a[1]), "r"(a[2]), "r"(a[3]), "r"(b0), "r"(b1));
}
__device__ __forceinline__ void split_bf16(float f, __nv_bfloat16& h, __nv_bfloat16& l){
  h = __float2bfloat16(f);
  l = __float2bfloat16(f - __bfloat162float(h));
}

// ---------------- 1) adjacency ----------------
__global__ void k_adj(const float* __restrict__ E){
  int i = blockIdx.x, j = threadIdx.x;
  __shared__ float Ei[16];
  __shared__ float red[512];
  if (j < 16) Ei[j] = E[i*16 + j];
  __syncthreads();
  float d = 0.f;
  #pragma unroll
  for (int c = 0; c < 16; c++) d = fmaf(Ei[c], E[j*16 + c], d);
  d = fmaxf(d, 0.f);
  red[j] = d; __syncthreads();
  for (int s = 256; s > 0; s >>= 1){ if (j < s) red[j] = fmaxf(red[j], red[j+s]); __syncthreads(); }
  float mx = red[0];
  __syncthreads();
  float e = __expf(d - mx);
  red[j] = e; __syncthreads();
  for (int s = 256; s > 0; s >>= 1){ if (j < s) red[j] += red[j+s]; __syncthreads(); }
  float a = e * (1.f / red[0]);
  __nv_bfloat16 h, l; split_bf16(a, h, l);
  g_Ah[i*512 + j] = h; g_Al[i*512 + j] = l;
}

// ---------------- 2) STE projections ----------------
__global__ void k_prep(const float* __restrict__ ne1, const float* __restrict__ ne2,
                       const float* __restrict__ Wq, const float* __restrict__ bq,
                       const float* __restrict__ Wk, const float* __restrict__ bk,
                       const float* __restrict__ Wv, const float* __restrict__ bv){
  int row = blockIdx.x, o = threadIdx.x;
  if (row < 768){
    const float* e = ne2 + row*32;
    float a = bq[o];
    #pragma unroll
    for (int d = 0; d < 32; d++) a = fmaf(e[d], Wq[d*64 + o], a);
    g_pq[row*64 + o] = a;
  } else if (row < 832){
    int b = row - 768;
    const float* e = ne1 + (b*12 + 11)*32;
    float a = bk[o];
    #pragma unroll
    for (int d = 0; d < 32; d++) a = fmaf(e[d], Wk[d*64 + o], a);
    g_pk[b*64 + o] = a;
  } else {
    int b = row - 832;
    const float* e = ne1 + (b*12 + 11)*32;
    float a = bv[o];
    #pragma unroll
    for (int d = 0; d < 32; d++) a = fmaf(e[d], Wv[d*64 + o], a);
    g_pv[b*64 + o] = a;
  }
}

// ---------------- 3) qkvu GEMM ----------------
__global__ void k_qkvu(const float* __restrict__ X, const float* __restrict__ Wq,
                       const float* __restrict__ Wk, const float* __restrict__ Wv,
                       const float* __restrict__ taw, const float* __restrict__ tab){
  int mode = blockIdx.x;
  int row0 = blockIdx.y * 64;
  const float* Wsrc = (mode==0) ? Wq + 2048 : (mode==1) ? Wk + 2048
                    : (mode==2) ? Wv + 2048 : taw;
  __shared__ float As[64][65];
  __shared__ float Bs[64][65];
  int tid = threadIdx.x;
  #pragma unroll
  for (int i = 0; i < 4; i++){
    int idx = tid + i*256;
    int r = idx >> 4, kq = idx & 15;
    float4 a4 = *(const float4*)(X + (size_t)(row0 + r)*64 + kq*4);
    As[r][kq*4+0]=a4.x; As[r][kq*4+1]=a4.y; As[r][kq*4+2]=a4.z; As[r][kq*4+3]=a4.w;
    float4 w4 = *(const float4*)(Wsrc + (size_t)r*64 + kq*4);
    Bs[r][kq*4+0]=w4.x; Bs[r][kq*4+1]=w4.y; Bs[r][kq*4+2]=w4.z; Bs[r][kq*4+3]=w4.w;
  }
  __syncthreads();
  int ty = tid >> 4, tx = tid & 15;
  float acc[4][4];
  #pragma unroll
  for (int i=0;i<4;i++){ acc[i][0]=0.f; acc[i][1]=0.f; acc[i][2]=0.f; acc[i][3]=0.f; }
  #pragma unroll 16
  for (int k = 0; k < 64; k++){
    float a[4], b[4];
    #pragma unroll
    for (int i=0;i<4;i++) a[i] = As[ty*4+i][k];
    #pragma unroll
    for (int j=0;j<4;j++) b[j] = Bs[k][tx*4+j];
    #pragma unroll
    for (int i=0;i<4;i++)
      #pragma unroll
      for (int j=0;j<4;j++) acc[i][j] = fmaf(a[i], b[j], acc[i][j]);
  }
  #pragma unroll
  for (int i=0;i<4;i++){
    int r = row0 + ty*4 + i;
    int bb = r >> 9;
    #pragma unroll
    for (int j=0;j<4;j++){
      int c = tx*4 + j;
      float v = acc[i][j];
      if (mode == 1)      v = fmaxf(v + g_pk[bb*64 + c], 0.f);
      else if (mode == 2) v = fmaxf(v + g_pv[bb*64 + c], 0.f);
      else if (mode == 3) v = v + tab[c];
      g_qkvu[(size_t)r*256 + mode*64 + c] = v;
    }
  }
}

// ---------------- 4) fused attention -> de (fp32 + bf16 hi/lo) ----------------
__global__ void k_attn2(const float* __restrict__ taw){
  const float* taw1 = taw + 4096;
  __shared__ float tw[64][64];
  __shared__ float qs[8][64], ks[8][64], vs[8][64];
  __shared__ float es[8][8][12];
  for (int i = threadIdx.x; i < 4096; i += 256) tw[i>>6][i&63] = taw1[i];
  __syncthreads();
  int w = threadIdx.x >> 5;
  int lane = threadIdx.x & 31;
  int bn = blockIdx.x*8 + w;
  int b = bn >> 9, n = bn & 511;
  const float* base = g_qkvu + (size_t)bn*256;
  int c0 = lane*2, c1 = c0 + 1;
  float u0  = base[192+c0], u1  = base[192+c1];
  qs[w][c0]=base[c0];     qs[w][c1]=base[c1];
  ks[w][c0]=base[64+c0];  ks[w][c1]=base[64+c1];
  vs[w][c0]=base[128+c0]; vs[w][c1]=base[128+c1];
  __syncwarp();
  float vw0[8], vw1[8];
  #pragma unroll
  for (int d = 0; d < 8; d++){
    float a0 = 0.f, a1 = 0.f;
    #pragma unroll
    for (int cp = 0; cp < 8; cp++){
      float vv = vs[w][d*8+cp];
      float2 t2 = *(const float2*)&tw[d*8+cp][c0];
      a0 = fmaf(vv, t2.x, a0); a1 = fmaf(vv, t2.y, a1);
    }
    vw0[d] = a0; vw1[d] = a1;
  }
  for (int task = lane; task < 96; task += 32){
    int d = task / 12, t = task - d*12;
    const float* pq = g_pq + (size_t)(b*12 + t)*64 + d*8;
    float e = 0.f;
    #pragma unroll
    for (int cp = 0; cp < 8; cp++){
      float q = fmaxf(qs[w][d*8+cp] + pq[cp], 0.f);
      e = fmaf(q, ks[w][d*8+cp], e);
    }
    es[w][d][t] = e;
  }
  __syncwarp();
  if (lane < 8){
    float mx = -1e30f;
    #pragma unroll
    for (int t=0;t<12;t++) mx = fmaxf(mx, es[w][lane][t]);
    float ssum = 0.f;
    #pragma unroll
    for (int t=0;t<12;t++){ float ex = __expf(es[w][lane][t]-mx); es[w][lane][t]=ex; ssum+=ex; }
    float inv = 1.f/ssum;
    #pragma unroll
    for (int t=0;t<12;t++) es[w][lane][t] *= inv;
  }
  __syncwarp();
  #pragma unroll
  for (int t = 0; t < 12; t++){
    float o0 = u0, o1 = u1;
    #pragma unroll
    for (int d = 0; d < 8; d++){
      float a = es[w][d][t];
      o0 = fmaf(a, vw0[d], o0); o1 = fmaf(a, vw1[d], o1);
    }
    size_t off = ((size_t)(b*12 + t)*512 + n)*64;
    *(float2*)(g_de + off + c0) = make_float2(o0, o1);
    __nv_bfloat16 h0,l0,h1,l1;
    split_bf16(o0,h0,l0); split_bf16(o1,h1,l1);
    __nv_bfloat162 hv; hv.x=h0; hv.y=h1;
    __nv_bfloat162 lv; lv.x=l0; lv.y=l1;
    *(__nv_bfloat162*)(g_deh + off + c0) = hv;
    *(__nv_bfloat162*)(g_del + off + c0) = lv;
  }
}

// ---------------- 5) weight gen: C = ne2 @ wp + w -> bf16 h/l, dead row-0 dropped ----------------
// dst 0: gcn1 weights (No=128) -> g_W1h/l ; dst 1: gcn2 (No=64) -> g_Wuh/l
// dst 2: gcn1 bias (Nc=128)   -> g_b1    ; dst 3: gcn2 bias (Nc=64) -> g_bu
__global__ void k_wgen(const float* __restrict__ Am, const float* __restrict__ Bw,
                       const float* __restrict__ g, int Nc, int dst){
  int col0 = blockIdx.x * 64, row0 = blockIdx.y * 64;
  __shared__ float As[64][33];
  __shared__ float Bs[32][65];
  int tid = threadIdx.x;
  #pragma unroll
  for (int i = 0; i < 2; i++){
    int idx = tid + i*256;
    { int r = idx >> 3, kq = idx & 7;
      float4 a4 = *(const float4*)(Am + (size_t)(row0 + r)*32 + kq*4);
      As[r][kq*4+0]=a4.x; As[r][kq*4+1]=a4.y; As[r][kq*4+2]=a4.z; As[r][kq*4+3]=a4.w; }
    { int r = idx >> 4, cq = idx & 15;
      float4 b4 = *(const float4*)(Bw + (size_t)r*Nc + col0 + cq*4);
      Bs[r][cq*4+0]=b4.x; Bs[r][cq*4+1]=b4.y; Bs[r][cq*4+2]=b4.z; Bs[r][cq*4+3]=b4.w; }
  }
  __syncthreads();
  int ty = tid >> 4, tx = tid & 15;
  float acc[4][4];
  #pragma unroll
  for (int i=0;i<4;i++){ acc[i][0]=0.f; acc[i][1]=0.f; acc[i][2]=0.f; acc[i][3]=0.f; }
  #pragma unroll
  for (int k = 0; k < 32; k++){
    float a[4], b[4];
    #pragma unroll
    for (int i=0;i<4;i++) a[i] = As[ty*4+i][k];
    #pragma unroll
    for (int j=0;j<4;j++) b[j] = Bs[k][tx*4+j];
    #pragma unroll
    for (int i=0;i<4;i++)
      #pragma unroll
      for (int j=0;j<4;j++) acc[i][j] = fmaf(a[i], b[j], acc[i][j]);
  }
  int No = (dst==0) ? 128 : 64;
  int GNo = 65*No;
  #pragma unroll
  for (int i=0;i<4;i++){
    int r = row0 + ty*4 + i;   // bt row
    #pragma unroll
    for (int j=0;j<4;j++){
      int c = col0 + tx*4 + j;
      float v = acc[i][j] + g[c];
      if (dst == 2)      g_b1[(size_t)r*128 + c] = v;
      else if (dst == 3) g_bu[(size_t)r*64 + c] = v;
      else {
        int seg = c / GNo, rem = c - seg*GNo;
        int ki = rem / No, o = rem - ki*No;
        if (ki >= 1){
          size_t off = (((size_t)r*3 + seg)*64 + (ki-1))*No + o;
          __nv_bfloat16 h, l; split_bf16(v, h, l);
          if (dst == 0){ g_W1h[off] = h; g_W1l[off] = l; }
          else         { g_Wuh[off] = h; g_Wul[off] = l; }
        }
      }
    }
  }
}

// ---------------- 6) HMMA batched adjacency GEMM (bf16 hi/lo 3-term) ----------------
// mode 0: y1 = A@X (fp32 + bf16 h/l)   mode 1: y2 = 2(A@X) - Z (fp32 + bf16 h/l)
__global__ void __launch_bounds__(256, 2) k_bmma(int src_id, int mode, int z_id){
  const __nv_bfloat16* __restrict__ Bh = src_id==0 ? g_deh : src_id==1 ? g_y1h : g_yzh;
  const __nv_bfloat16* __restrict__ Bl = src_id==0 ? g_del : src_id==1 ? g_y1l : g_yzl;
  const float* __restrict__ Z = z_id==0 ? g_de : g_yz;

  __shared__ __nv_bfloat16 sAh[2][128*24], sAl[2][128*24];
  __shared__ __nv_bfloat16 sXh[2][16*72],  sXl[2][16*72];

  int bt = blockIdx.y, m0 = blockIdx.x * 128;
  int tid = threadIdx.x, wid = tid >> 5, lane = tid & 31;
  int warp_m = wid >> 1, warp_n = wid & 1;

  uint32_t uAh[2] = { s2u(sAh[0]), s2u(sAh[1]) };
  uint32_t uAl[2] = { s2u(sAl[0]), s2u(sAl[1]) };
  uint32_t uXh[2] = { s2u(sXh[0]), s2u(sXh[1]) };
  uint32_t uXl[2] = { s2u(sXl[0]), s2u(sXl[1]) };

  int arow = tid >> 1, aq = tid & 1;
  int xr = (tid & 127) >> 3, xq = tid & 7;
  bool xhi = tid < 128;

  auto load_chunk = [&](int c, int buf){
    int k0 = c * 16;
    size_t ga = (size_t)(m0 + arow)*512 + k0 + aq*8;
    cp16(uAh[buf] + arow*48 + aq*16, g_Ah + ga);
    cp16(uAl[buf] + arow*48 + aq*16, g_Al + ga);
    size_t gx = ((size_t)bt*512 + k0 + xr)*64 + xq*8;
    if (xhi) cp16(uXh[buf] + xr*144 + xq*16, Bh + gx);
    else     cp16(uXl[buf] + xr*144 + xq*16, Bl + gx);
  };

  float acc[2][4][4];
  #pragma unroll
  for (int mi=0;mi<2;mi++)
    #pragma unroll
    for (int nn=0;nn<4;nn++)
      #pragma unroll
      for (int j=0;j<4;j++) acc[mi][nn][j] = 0.f;

  load_chunk(0, 0);
  asm volatile("cp.async.commit_group;" ::: "memory");

  uint32_t lrow = lane & 15;
  uint32_t lk = (lane >> 4) << 4;

  for (int c = 0; c < 32; c++){
    int buf = c & 1;
    if (c < 31){
      load_chunk(c + 1, buf ^ 1);
      asm volatile("cp.async.commit_group;" ::: "memory");
      asm volatile("cp.async.wait_group 1;" ::: "memory");
    } else {
      asm volatile("cp.async.wait_group 0;" ::: "memory");
    }
    __syncthreads();

    uint32_t ah[2][4], al[2][4], bh[2][4], bl[2][4];
    #pragma unroll
    for (int mi = 0; mi < 2; mi++){
      uint32_t aoff = (uint32_t)(warp_m*32 + mi*16 + lrow)*48 + lk;
      ldm_x4(ah[mi], uAh[buf] + aoff);
      ldm_x4(al[mi], uAl[buf] + aoff);
    }
    #pragma unroll
    for (int np = 0; np < 2; np++){
      uint32_t boff = lrow*144 + (uint32_t)(warp_n*32 + np*16)*2 + lk;
      ldm_x4t(bh[np], uXh[buf] + boff);
      ldm_x4t(bl[np], uXl[buf] + boff);
    }
    #pragma unroll
    for (int mi = 0; mi < 2; mi++){
      #pragma unroll
      for (int nn = 0; nn < 4; nn++){
        int np = nn >> 1, sub = (nn & 1) * 2;
        mma_bf16(acc[mi][nn], ah[mi], bh[np][sub], bh[np][sub+1]);
        mma_bf16(acc[mi][nn], ah[mi], bl[np][sub], bl[np][sub+1]);
        mma_bf16(acc[mi][nn], al[mi], bh[np][sub], bh[np][sub+1]);
      }
    }
    __syncthreads();
  }

  int rbase = m0 + warp_m*32 + (lane >> 2);
  int cbase = warp_n*32 + (lane & 3)*2;
  #pragma unroll
  for (int mi = 0; mi < 2; mi++){
    #pragma unroll
    for (int nn = 0; nn < 4; nn++){
      int col = cbase + nn*8;
      #pragma unroll
      for (int half = 0; half < 2; half++){
        int row = rbase + mi*16 + half*8;
        size_t off = ((size_t)bt*512 + row)*64 + col;
        float v0 = acc[mi][nn][half*2], v1 = acc[mi][nn][half*2+1];
        if (mode == 1){
          float2 z = *(const float2*)(Z + off);
          v0 = 2.f*v0 - z.x; v1 = 2.f*v1 - z.y;
        }
        float* Of = mode == 0 ? g_y1 : g_y2;
        __nv_bfloat16* Oh = mode == 0 ? g_y1h : g_y2h;
        __nv_bfloat16* Ol = mode == 0 ? g_y1l : g_y2l;
        *(float2*)(Of + off) = make_float2(v0, v1);
        __nv_bfloat16 h0,l0,h1,l1;
        split_bf16(v0,h0,l0); split_bf16(v1,h1,l1);
        __nv_bfloat162 hv; hv.x=h0; hv.y=h1;
        __nv_bfloat162 lv; lv.x=l0; lv.y=l1;
        *(__nv_bfloat162*)(Oh + off) = hv;
        *(__nv_bfloat162*)(Ol + off) = lv;
      }
    }
  }
}

// ---------------- 7) HMMA combine GEMM: act([Y0|Y1|Y2] @ W[bt] + b) ----------------
// WHICH 0: gcn1 -> ct==0: yz = sigmoid*de (fp32+h/l); ct==1: rg = sigmoid
// WHICH 1: gcn2 -> hc = tanh
template<int WHICH>
__global__ void __launch_bounds__(256, 2) k_combT(){
  constexpr int No = WHICH ? 64 : 128;
  const __nv_bfloat16* __restrict__ Y0h = WHICH ? g_yzh : g_deh;
  const __nv_bfloat16* __restrict__ Y0l = WHICH ? g_yzl : g_del;
  const __nv_bfloat16* __restrict__ Wh  = WHICH ? g_Wuh : g_W1h;
  const __nv_bfloat16* __restrict__ Wl  = WHICH ? g_Wul : g_W1l;

  __shared__ __nv_bfloat16 sAh[2][128*24], sAl[2][128*24];
  __shared__ __nv_bfloat16 sXh[2][16*72],  sXl[2][16*72];

  int bt = blockIdx.z, n0 = blockIdx.y * 128, ct = blockIdx.x;
  int tid = threadIdx.x, wid = tid >> 5, lane = tid & 31;
  int warp_m = wid >> 1, warp_n = wid & 1;

  uint32_t uAh[2] = { s2u(sAh[0]), s2u(sAh[1]) };
  uint32_t uAl[2] = { s2u(sAl[0]), s2u(sAl[1]) };
  uint32_t uXh[2] = { s2u(sXh[0]), s2u(sXh[1]) };
  uint32_t uXl[2] = { s2u(sXl[0]), s2u(sXl[1]) };

  int arow = tid >> 1, aq = tid & 1;
  int xr = (tid & 127) >> 3, xq = tid & 7;
  bool xhi = tid < 128;

  auto load_chunk = [&](int c, int buf){
    int seg = c >> 2, kin0 = (c & 3) * 16;
    const __nv_bfloat16* Yh = seg==0 ? Y0h : seg==1 ? g_y1h : g_y2h;
    const __nv_bfloat16* Yl = seg==0 ? Y0l : seg==1 ? g_y1l : g_y2l;
    size_t ga = ((size_t)bt*512 + n0 + arow)*64 + kin0 + aq*8;
    cp16(uAh[buf] + arow*48 + aq*16, Yh + ga);
    cp16(uAl[buf] + arow*48 + aq*16, Yl + ga);
    size_t gw = (((size_t)bt*3 + seg)*64 + kin0 + xr)*No + ct*64 + xq*8;
    if (xhi) cp16(uXh[buf] + xr*144 + xq*16, Wh + gw);
    else     cp16(uXl[buf] + xr*144 + xq*16, Wl + gw);
  };

  float acc[2][4][4];
  #pragma unroll
  for (int mi=0;mi<2;mi++)
    #pragma unroll
    for (int nn=0;nn<4;nn++)
      #pragma unroll
      for (int j=0;j<4;j++) acc[mi][nn][j] = 0.f;

  load_chunk(0, 0);
  asm volatile("cp.async.commit_group;" ::: "memory");

  uint32_t lrow = lane & 15;
  uint32_t lk = (lane >> 4) << 4;

  for (int c = 0; c < 12; c++){
    int buf = c & 1;
    if (c < 11){
      load_chunk(c + 1, buf ^ 1);
      asm volatile("cp.async.commit_group;" ::: "memory");
      asm volatile("cp.async.wait_group 1;" ::: "memory");
    } else {
      asm volatile("cp.async.wait_group 0;" ::: "memory");
    }
    __syncthreads();

    uint32_t ah[2][4], al[2][4], bh[2][4], bl[2][4];
    #pragma unroll
    for (int mi = 0; mi < 2; mi++){
      uint32_t aoff = (uint32_t)(warp_m*32 + mi*16 + lrow)*48 + lk;
      ldm_x4(ah[mi], uAh[buf] + aoff);
      ldm_x4(al[mi], uAl[buf] + aoff);
    }
    #pragma unroll
    for (int np = 0; np < 2; np++){
      uint32_t boff = lrow*144 + (uint32_t)(warp_n*32 + np*16)*2 + lk;
      ldm_x4t(bh[np], uXh[buf] + boff);
      ldm_x4t(bl[np], uXl[buf] + boff);
    }
    #pragma unroll
    for (int mi = 0; mi < 2; mi++){
      #pragma unroll
      for (int nn = 0; nn < 4; nn++){
        int np = nn >> 1, sub = (nn & 1) * 2;
        mma_bf16(acc[mi][nn], ah[mi], bh[np][sub], bh[np][sub+1]);
        mma_bf16(acc[mi][nn], ah[mi], bl[np][sub], bl[np][sub+1]);
        mma_bf16(acc[mi][nn], al[mi], bh[np][sub], bh[np][sub+1]);
      }
    }
    __syncthreads();
  }

  int rbase = n0 + warp_m*32 + (lane >> 2);
  int cbase = warp_n*32 + (lane & 3)*2;
  #pragma unroll
  for (int mi = 0; mi < 2; mi++){
    #pragma unroll
    for (int nn = 0; nn < 4; nn++){
      int col = cbase + nn*8;
      int gcol = ct*64 + col;
      #pragma unroll
      for (int half = 0; half < 2; half++){
        int row = rbase + mi*16 + half*8;
        size_t off = ((size_t)bt*512 + row)*64 + col;   // col in [0,64)
        float v0 = acc[mi][nn][half*2], v1 = acc[mi][nn][half*2+1];
        if (WHICH == 0){
          v0 += g_b1[(size_t)bt*128 + gcol];
          v1 += g_b1[(size_t)bt*128 + gcol + 1];
          v0 = 1.f/(1.f + __expf(-v0));
          v1 = 1.f/(1.f + __expf(-v1));
          if (ct == 0){
            float2 de = *(const float2*)(g_de + off);
            float z0 = v0 * de.x, z1 = v1 * de.y;
            *(float2*)(g_yz + off) = make_float2(z0, z1);
            __nv_bfloat16 h0,l0,h1,l1;
            split_bf16(z0,h0,l0); split_bf16(z1,h1,l1);
            __nv_bfloat162 hv; hv.x=h0; hv.y=h1;
            __nv_bfloat162 lv; lv.x=l0; lv.y=l1;
            *(__nv_bfloat162*)(g_yzh + off) = hv;
            *(__nv_bfloat162*)(g_yzl + off) = lv;
          } else {
            *(float2*)(g_rg + off) = make_float2(v0, v1);
          }
        } else {
          v0 = tanhf(v0 + g_bu[(size_t)bt*64 + gcol]);
          v1 = tanhf(v1 + g_bu[(size_t)bt*64 + gcol + 1]);
          *(float2*)(g_hc + off) = make_float2(v0, v1);
        }
      }
    }
  }
}

// ---------------- 8) final projection ----------------
__global__ void k_out(const float* __restrict__ outw, const float* __restrict__ outb,
                      float* __restrict__ out){
  int gw = blockIdx.x*8 + (threadIdx.x >> 5);
  int lane = threadIdx.x & 31;
  size_t mn = (size_t)gw;
  int m = gw >> 9;
  int t = m % 12;
  size_t base = mn << 6;
  float s = 0.f;
  #pragma unroll
  for (int ii = 0; ii < 2; ii++){
    int i = lane + ii*32;
    float rg = g_rg[base + i];
    float de = g_de[base + i];
    float hc = g_hc[base + i];
    float st = fmaf(rg, de - hc, hc);
    s = fmaf(st, outw[t*64 + i], s);
  }
  #pragma unroll
  for (int off = 16; off > 0; off >>= 1) s += __shfl_xor_sync(0xffffffffu, s, off);
  if (lane == 0) out[mn] = s + outb[t];
}

// ---------------- launch ----------------
extern "C" void kernel_launch(void* const* d_in, const int* in_sizes, int n_in,
                              void* d_out, int out_size){
  (void)in_sizes; (void)n_in; (void)out_size;
  const float* hn  = (const float*)d_in[2];
  const float* ne1 = (const float*)d_in[3];
  const float* ne2 = (const float*)d_in[4];
  const float* E   = (const float*)d_in[5];
  const float* Wq  = (const float*)d_in[6];
  const float* bq  = (const float*)d_in[7];
  const float* Wk  = (const float*)d_in[8];
  const float* bk  = (const float*)d_in[9];
  const float* Wv  = (const float*)d_in[10];
  const float* bv  = (const float*)d_in[11];
  const float* taw = (const float*)d_in[12];
  const float* tab = (const float*)d_in[13];
  const float* gwp = (const float*)d_in[14];
  const float* gw  = (const float*)d_in[15];
  const float* gbp = (const float*)d_in[16];
  const float* gb  = (const float*)d_in[17];
  const float* uwp = (const float*)d_in[18];
  const float* uw  = (const float*)d_in[19];
  const float* ubp = (const float*)d_in[20];
  const float* ub  = (const float*)d_in[21];
  const float* outw= (const float*)d_in[22];
  const float* outb= (const float*)d_in[23];
  float* out = (float*)d_out;

  k_adj<<<512, 512>>>(E);
  k_prep<<<896, 64>>>(ne1, ne2, Wq, bq, Wk, bk, Wv, bv);
  k_qkvu<<<dim3(4, 512), 256>>>(hn, Wq, Wk, Wv, taw, tab);
  k_attn2<<<4096, 256>>>(taw);
  k_wgen<<<dim3(390, 12), 256>>>(ne2, gwp, gw, 24960, 0);
  k_wgen<<<dim3(195, 12), 256>>>(ne2, uwp, uw, 12480, 1);
  k_wgen<<<dim3(2, 12), 256>>>(ne2, gbp, gb, 128, 2);
  k_wgen<<<dim3(1, 12), 256>>>(ne2, ubp, ub, 64, 3);
  k_bmma<<<dim3(4, 768), 256>>>(0, 0, 0);        // y1 = A @ de
  k_bmma<<<dim3(4, 768), 256>>>(1, 1, 0);        // y2 = 2A@y1 - de
  k_combT<0><<<dim3(2, 4, 768), 256>>>();        // yz / rg
  k_bmma<<<dim3(4, 768), 256>>>(2, 0, 0);        // y1 = A @ yz
  k_bmma<<<dim3(4, 768), 256>>>(1, 1, 2);        // y2 = 2A@y1 - yz
  k_combT<1><<<dim3(1, 4, 768), 256>>>();        // hc
  k_out<<<49152, 256>>>(outw, outb, out);
}

// round 6
// speedup vs baseline: 1.9889x; 1.0617x over previous
#include <cuda_runtime.h>
#include <cuda_bf16.h>
#include <math.h>
#include <stdint.h>

// B=64, T=12, N=512, H=64, TD=32, ED=16, CHEB_K=3, D_HEADS=8, M=768
constexpr size_t NF = (size_t)768*512*64;

// ---------------- device scratch ----------------
__device__ float g_Af[512*512];
__device__ __nv_bfloat16 g_Ah[512*512], g_Al[512*512];
__device__ __nv_bfloat16 g_M2h[512*512], g_M2l[512*512];
__device__ float g_pq[768*64], g_pk[64*64], g_pv[64*64];
__device__ float g_qkvu[(size_t)32768*256];
__device__ float g_de[NF], g_yz[NF], g_hc[NF], g_rg[NF];
__device__ __nv_bfloat16 g_deh[NF], g_del[NF], g_y1h[NF], g_y1l[NF];
__device__ __nv_bfloat16 g_y2h[NF], g_y2l[NF], g_yzh[NF], g_yzl[NF];
__device__ __nv_bfloat16 g_W1h[(size_t)768*3*64*128], g_W1l[(size_t)768*3*64*128];
__device__ __nv_bfloat16 g_Wuh[(size_t)768*3*64*64],  g_Wul[(size_t)768*3*64*64];
__device__ float g_b1[768*128], g_bu[768*64];

// ---------------- ptx helpers (sm_80+ baseline only) ----------------
__device__ __forceinline__ uint32_t s2u(const void* p){
  uint32_t a;
  asm("{ .reg .u64 t; cvta.to.shared.u64 t, %1; cvt.u32.u64 %0, t; }" : "=r"(a) : "l"(p));
  return a;
}
__device__ __forceinline__ void cp16(uint32_t dst, const void* src){
  asm volatile("cp.async.cg.shared.global [%0], [%1], 16;" :: "r"(dst), "l"(src) : "memory");
}
__device__ __forceinline__ void ldm_x4(uint32_t* r, uint32_t addr){
  asm volatile("ldmatrix.sync.aligned.m8n8.x4.shared.b16 {%0,%1,%2,%3}, [%4];"
    : "=r"(r[0]), "=r"(r[1]), "=r"(r[2]), "=r"(r[3]) : "r"(addr));
}
__device__ __forceinline__ void ldm_x4t(uint32_t* r, uint32_t addr){
  asm volatile("ldmatrix.sync.aligned.m8n8.x4.trans.shared.b16 {%0,%1,%2,%3}, [%4];"
    : "=r"(r[0]), "=r"(r[1]), "=r"(r[2]), "=r"(r[3]) : "r"(addr));
}
__device__ __forceinline__ void mma_bf16(float* c, const uint32_t* a, uint32_t b0, uint32_t b1){
  asm volatile(
    "mma.sync.aligned.m16n8k16.row.col.f32.bf16.bf16.f32 "
    "{%0,%1,%2,%3}, {%4,%5,%6,%7}, {%8,%9}, {%0,%1,%2,%3};"
    : "+f"(c[0]), "+f"(c[1]), "+f"(c[2]), "+f"(c[3])
    : "r"(a[0]), "r"(a[1]), "r"(a[2]), "r"(a[3]), "r"(b0), "r"(b1));
}
__device__ __forceinline__ void split_bf16(float f, __nv_bfloat16& h, __nv_bfloat16& l){
  h = __float2bfloat16(f);
  l = __float2bfloat16(f - __bfloat162float(h));
}

// ---------------- 1) adjacency (fp32 + bf16 hi/lo) ----------------
__global__ void k_adj(const float* __restrict__ E){
  int i = blockIdx.x, j = threadIdx.x;
  __shared__ float Ei[16];
  __shared__ float red[512];
  if (j < 16) Ei[j] = E[i*16 + j];
  __syncthreads();
  float d = 0.f;
  #pragma unroll
  for (int c = 0; c < 16; c++) d = fmaf(Ei[c], E[j*16 + c], d);
  d = fmaxf(d, 0.f);
  red[j] = d; __syncthreads();
  for (int s = 256; s > 0; s >>= 1){ if (j < s) red[j] = fmaxf(red[j], red[j+s]); __syncthreads(); }
  float mx = red[0];
  __syncthreads();
  float e = __expf(d - mx);
  red[j] = e; __syncthreads();
  for (int s = 256; s > 0; s >>= 1){ if (j < s) red[j] += red[j+s]; __syncthreads(); }
  float a = e * (1.f / red[0]);
  g_Af[i*512 + j] = a;
  __nv_bfloat16 h, l; split_bf16(a, h, l);
  g_Ah[i*512 + j] = h; g_Al[i*512 + j] = l;
}

// ---------------- 1b) M2 = 2*A@A (fp32 SIMT, tiny) -> bf16 hi/lo ----------------
__global__ void k_a2(){
  int row0 = blockIdx.x * 128, col0 = blockIdx.y * 64;
  __shared__ float As[128][17];
  __shared__ __align__(16) float Bs[16][64];
  int tid = threadIdx.x;
  int tx = tid & 7, ty = tid >> 3;
  float acc[8][8];
  #pragma unroll
  for (int i=0;i<8;i++)
    #pragma unroll
    for (int j=0;j<8;j++) acc[i][j] = 0.f;
  for (int k0 = 0; k0 < 512; k0 += 16){
    #pragma unroll
    for (int i = 0; i < 4; i++){
      int idx = tid + i*128;
      int r = idx >> 2, kq = idx & 3;
      float4 a4 = *(const float4*)(g_Af + (size_t)(row0 + r)*512 + k0 + kq*4);
      As[r][kq*4+0]=a4.x; As[r][kq*4+1]=a4.y; As[r][kq*4+2]=a4.z; As[r][kq*4+3]=a4.w;
    }
    #pragma unroll
    for (int i = 0; i < 2; i++){
      int idx = tid + i*128;
      int r = idx >> 4, cq = idx & 15;
      float4 b4 = *(const float4*)(g_Af + (size_t)(k0 + r)*512 + col0 + cq*4);
      *(float4*)&Bs[r][cq*4] = b4;
    }
    __syncthreads();
    #pragma unroll
    for (int k = 0; k < 16; k++){
      float a[8], b[8];
      #pragma unroll
      for (int i=0;i<8;i++) a[i] = As[ty*8+i][k];
      float4 b0 = *(const float4*)&Bs[k][tx*8];
      float4 b1 = *(const float4*)&Bs[k][tx*8+4];
      b[0]=b0.x; b[1]=b0.y; b[2]=b0.z; b[3]=b0.w;
      b[4]=b1.x; b[5]=b1.y; b[6]=b1.z; b[7]=b1.w;
      #pragma unroll
      for (int i=0;i<8;i++)
        #pragma unroll
        for (int j=0;j<8;j++) acc[i][j] = fmaf(a[i], b[j], acc[i][j]);
    }
    __syncthreads();
  }
  #pragma unroll
  for (int i=0;i<8;i++){
    size_t r = row0 + ty*8 + i;
    #pragma unroll
    for (int j=0;j<8;j++){
      float v = 2.f * acc[i][j];
      __nv_bfloat16 h, l; split_bf16(v, h, l);
      g_M2h[r*512 + col0 + tx*8 + j] = h;
      g_M2l[r*512 + col0 + tx*8 + j] = l;
    }
  }
}

// ---------------- 2) STE projections ----------------
__global__ void k_prep(const float* __restrict__ ne1, const float* __restrict__ ne2,
                       const float* __restrict__ Wq, const float* __restrict__ bq,
                       const float* __restrict__ Wk, const float* __restrict__ bk,
                       const float* __restrict__ Wv, const float* __restrict__ bv){
  int row = blockIdx.x, o = threadIdx.x;
  if (row < 768){
    const float* e = ne2 + row*32;
    float a = bq[o];
    #pragma unroll
    for (int d = 0; d < 32; d++) a = fmaf(e[d], Wq[d*64 + o], a);
    g_pq[row*64 + o] = a;
  } else if (row < 832){
    int b = row - 768;
    const float* e = ne1 + (b*12 + 11)*32;
    float a = bk[o];
    #pragma unroll
    for (int d = 0; d < 32; d++) a = fmaf(e[d], Wk[d*64 + o], a);
    g_pk[b*64 + o] = a;
  } else {
    int b = row - 832;
    const float* e = ne1 + (b*12 + 11)*32;
    float a = bv[o];
    #pragma unroll
    for (int d = 0; d < 32; d++) a = fmaf(e[d], Wv[d*64 + o], a);
    g_pv[b*64 + o] = a;
  }
}

// ---------------- 3) qkvu GEMM ----------------
__global__ void k_qkvu(const float* __restrict__ X, const float* __restrict__ Wq,
                       const float* __restrict__ Wk, const float* __restrict__ Wv,
                       const float* __restrict__ taw, const float* __restrict__ tab){
  int mode = blockIdx.x;
  int row0 = blockIdx.y * 64;
  const float* Wsrc = (mode==0) ? Wq + 2048 : (mode==1) ? Wk + 2048
                    : (mode==2) ? Wv + 2048 : taw;
  __shared__ float As[64][65];
  __shared__ float Bs[64][65];
  int tid = threadIdx.x;
  #pragma unroll
  for (int i = 0; i < 4; i++){
    int idx = tid + i*256;
    int r = idx >> 4, kq = idx & 15;
    float4 a4 = *(const float4*)(X + (size_t)(row0 + r)*64 + kq*4);
    As[r][kq*4+0]=a4.x; As[r][kq*4+1]=a4.y; As[r][kq*4+2]=a4.z; As[r][kq*4+3]=a4.w;
    float4 w4 = *(const float4*)(Wsrc + (size_t)r*64 + kq*4);
    Bs[r][kq*4+0]=w4.x; Bs[r][kq*4+1]=w4.y; Bs[r][kq*4+2]=w4.z; Bs[r][kq*4+3]=w4.w;
  }
  __syncthreads();
  int ty = tid >> 4, tx = tid & 15;
  float acc[4][4];
  #pragma unroll
  for (int i=0;i<4;i++){ acc[i][0]=0.f; acc[i][1]=0.f; acc[i][2]=0.f; acc[i][3]=0.f; }
  #pragma unroll 16
  for (int k = 0; k < 64; k++){
    float a[4], b[4];
    #pragma unroll
    for (int i=0;i<4;i++) a[i] = As[ty*4+i][k];
    #pragma unroll
    for (int j=0;j<4;j++) b[j] = Bs[k][tx*4+j];
    #pragma unroll
    for (int i=0;i<4;i++)
      #pragma unroll
      for (int j=0;j<4;j++) acc[i][j] = fmaf(a[i], b[j], acc[i][j]);
  }
  #pragma unroll
  for (int i=0;i<4;i++){
    int r = row0 + ty*4 + i;
    int bb = r >> 9;
    #pragma unroll
    for (int j=0;j<4;j++){
      int c = tx*4 + j;
      float v = acc[i][j];
      if (mode == 1)      v = fmaxf(v + g_pk[bb*64 + c], 0.f);
      else if (mode == 2) v = fmaxf(v + g_pv[bb*64 + c], 0.f);
      else if (mode == 3) v = v + tab[c];
      g_qkvu[(size_t)r*256 + mode*64 + c] = v;
    }
  }
}

// ---------------- 4) fused attention -> de (fp32 + bf16 hi/lo) ----------------
__global__ void k_attn2(const float* __restrict__ taw){
  const float* taw1 = taw + 4096;
  __shared__ float tw[64][64];
  __shared__ float qs[8][64], ks[8][64], vs[8][64];
  __shared__ float es[8][8][12];
  for (int i = threadIdx.x; i < 4096; i += 256) tw[i>>6][i&63] = taw1[i];
  __syncthreads();
  int w = threadIdx.x >> 5;
  int lane = threadIdx.x & 31;
  int bn = blockIdx.x*8 + w;
  int b = bn >> 9, n = bn & 511;
  const float* base = g_qkvu + (size_t)bn*256;
  int c0 = lane*2, c1 = c0 + 1;
  float u0  = base[192+c0], u1  = base[192+c1];
  qs[w][c0]=base[c0];     qs[w][c1]=base[c1];
  ks[w][c0]=base[64+c0];  ks[w][c1]=base[64+c1];
  vs[w][c0]=base[128+c0]; vs[w][c1]=base[128+c1];
  __syncwarp();
  float vw0[8], vw1[8];
  #pragma unroll
  for (int d = 0; d < 8; d++){
    float a0 = 0.f, a1 = 0.f;
    #pragma unroll
    for (int cp = 0; cp < 8; cp++){
      float vv = vs[w][d*8+cp];
      float2 t2 = *(const float2*)&tw[d*8+cp][c0];
      a0 = fmaf(vv, t2.x, a0); a1 = fmaf(vv, t2.y, a1);
    }
    vw0[d] = a0; vw1[d] = a1;
  }
  for (int task = lane; task < 96; task += 32){
    int d = task / 12, t = task - d*12;
    const float* pq = g_pq + (size_t)(b*12 + t)*64 + d*8;
    float e = 0.f;
    #pragma unroll
    for (int cp = 0; cp < 8; cp++){
      float q = fmaxf(qs[w][d*8+cp] + pq[cp], 0.f);
      e = fmaf(q, ks[w][d*8+cp], e);
    }
    es[w][d][t] = e;
  }
  __syncwarp();
  if (lane < 8){
    float mx = -1e30f;
    #pragma unroll
    for (int t=0;t<12;t++) mx = fmaxf(mx, es[w][lane][t]);
    float ssum = 0.f;
    #pragma unroll
    for (int t=0;t<12;t++){ float ex = __expf(es[w][lane][t]-mx); es[w][lane][t]=ex; ssum+=ex; }
    float inv = 1.f/ssum;
    #pragma unroll
    for (int t=0;t<12;t++) es[w][lane][t] *= inv;
  }
  __syncwarp();
  #pragma unroll
  for (int t = 0; t < 12; t++){
    float o0 = u0, o1 = u1;
    #pragma unroll
    for (int d = 0; d < 8; d++){
      float a = es[w][d][t];
      o0 = fmaf(a, vw0[d], o0); o1 = fmaf(a, vw1[d], o1);
    }
    size_t off = ((size_t)(b*12 + t)*512 + n)*64;
    *(float2*)(g_de + off + c0) = make_float2(o0, o1);
    __nv_bfloat16 h0,l0,h1,l1;
    split_bf16(o0,h0,l0); split_bf16(o1,h1,l1);
    __nv_bfloat162 hv; hv.x=h0; hv.y=h1;
    __nv_bfloat162 lv; lv.x=l0; lv.y=l1;
    *(__nv_bfloat162*)(g_deh + off + c0) = hv;
    *(__nv_bfloat162*)(g_del + off + c0) = lv;
  }
}

// ---------------- 5) weight gen ----------------
__global__ void k_wgen(const float* __restrict__ Am, const float* __restrict__ Bw,
                       const float* __restrict__ g, int Nc, int dst){
  int col0 = blockIdx.x * 64, row0 = blockIdx.y * 64;
  __shared__ float As[64][33];
  __shared__ float Bs[32][65];
  int tid = threadIdx.x;
  #pragma unroll
  for (int i = 0; i < 2; i++){
    int idx = tid + i*256;
    { int r = idx >> 3, kq = idx & 7;
      float4 a4 = *(const float4*)(Am + (size_t)(row0 + r)*32 + kq*4);
      As[r][kq*4+0]=a4.x; As[r][kq*4+1]=a4.y; As[r][kq*4+2]=a4.z; As[r][kq*4+3]=a4.w; }
    { int r = idx >> 4, cq = idx & 15;
      float4 b4 = *(const float4*)(Bw + (size_t)r*Nc + col0 + cq*4);
      Bs[r][cq*4+0]=b4.x; Bs[r][cq*4+1]=b4.y; Bs[r][cq*4+2]=b4.z; Bs[r][cq*4+3]=b4.w; }
  }
  __syncthreads();
  int ty = tid >> 4, tx = tid & 15;
  float acc[4][4];
  #pragma unroll
  for (int i=0;i<4;i++){ acc[i][0]=0.f; acc[i][1]=0.f; acc[i][2]=0.f; acc[i][3]=0.f; }
  #pragma unroll
  for (int k = 0; k < 32; k++){
    float a[4], b[4];
    #pragma unroll
    for (int i=0;i<4;i++) a[i] = As[ty*4+i][k];
    #pragma unroll
    for (int j=0;j<4;j++) b[j] = Bs[k][tx*4+j];
    #pragma unroll
    for (int i=0;i<4;i++)
      #pragma unroll
      for (int j=0;j<4;j++) acc[i][j] = fmaf(a[i], b[j], acc[i][j]);
  }
  int No = (dst==0) ? 128 : 64;
  int GNo = 65*No;
  #pragma unroll
  for (int i=0;i<4;i++){
    int r = row0 + ty*4 + i;
    #pragma unroll
    for (int j=0;j<4;j++){
      int c = col0 + tx*4 + j;
      float v = acc[i][j] + g[c];
      if (dst == 2)      g_b1[(size_t)r*128 + c] = v;
      else if (dst == 3) g_bu[(size_t)r*64 + c] = v;
      else {
        int seg = c / GNo, rem = c - seg*GNo;
        int ki = rem / No, o = rem - ki*No;
        if (ki >= 1){
          size_t off = (((size_t)r*3 + seg)*64 + (ki-1))*No + o;
          __nv_bfloat16 h, l; split_bf16(v, h, l);
          if (dst == 0){ g_W1h[off] = h; g_W1l[off] = l; }
          else         { g_Wuh[off] = h; g_Wul[off] = l; }
        }
      }
    }
  }
}

// ---------------- 6) dual HMMA: y1 = A@X, y2 = M2@X - X (bf16 hi/lo, 3-term) ----------------
constexpr int SMB = 58368;
// dynamic smem byte offsets (double-buffered)
constexpr int OAH = 0;       // 2 x 6144 (128 rows x 48B)
constexpr int OAL = 12288;
constexpr int OMH = 24576;
constexpr int OML = 36864;
constexpr int OXH = 49152;   // 2 x 2304 (16 rows x 144B)
constexpr int OXL = 53760;

__global__ void __launch_bounds__(256, 2) k_bmma2(int from_yz){
  extern __shared__ __align__(16) char dyn[];
  uint32_t sb = s2u(dyn);
  const __nv_bfloat16* __restrict__ Xh = from_yz ? g_yzh : g_deh;
  const __nv_bfloat16* __restrict__ Xl = from_yz ? g_yzl : g_del;
  const float* __restrict__ Z = from_yz ? g_yz : g_de;

  int bt = blockIdx.y, m0 = blockIdx.x * 128;
  int tid = threadIdx.x, wid = tid >> 5, lane = tid & 31;
  int warp_m = wid >> 1, warp_n = wid & 1;

  int arow = tid >> 1, aq = tid & 1;
  int xr = (tid & 127) >> 3, xq = tid & 7;
  bool xhi = tid < 128;

  auto load_chunk = [&](int c, int buf){
    int k0 = c * 16;
    size_t ga = (size_t)(m0 + arow)*512 + k0 + aq*8;
    uint32_t so = (uint32_t)buf*6144 + arow*48 + aq*16;
    cp16(sb + OAH + so, g_Ah + ga);
    cp16(sb + OAL + so, g_Al + ga);
    cp16(sb + OMH + so, g_M2h + ga);
    cp16(sb + OML + so, g_M2l + ga);
    size_t gx = ((size_t)bt*512 + k0 + xr)*64 + xq*8;
    uint32_t xo = (uint32_t)buf*2304 + xr*144 + xq*16;
    if (xhi) cp16(sb + OXH + xo, Xh + gx);
    else     cp16(sb + OXL + xo, Xl + gx);
  };

  float acc1[2][4][4], acc2[2][4][4];
  #pragma unroll
  for (int mi=0;mi<2;mi++)
    #pragma unroll
    for (int nn=0;nn<4;nn++)
      #pragma unroll
      for (int j=0;j<4;j++){ acc1[mi][nn][j] = 0.f; acc2[mi][nn][j] = 0.f; }

  load_chunk(0, 0);
  asm volatile("cp.async.commit_group;" ::: "memory");

  uint32_t lrow = lane & 15;
  uint32_t lk = (lane >> 4) << 4;

  for (int c = 0; c < 32; c++){
    int buf = c & 1;
    if (c < 31){
      load_chunk(c + 1, buf ^ 1);
      asm volatile("cp.async.commit_group;" ::: "memory");
      asm volatile("cp.async.wait_group 1;" ::: "memory");
    } else {
      asm volatile("cp.async.wait_group 0;" ::: "memory");
    }
    __syncthreads();

    uint32_t aoff = (uint32_t)buf*6144 + (uint32_t)(warp_m*32 + lrow)*48 + lk;
    uint32_t boff = (uint32_t)buf*2304 + lrow*144 + (uint32_t)(warp_n*32)*2 + lk;

    uint32_t bh[2][4], bl[2][4];
    #pragma unroll
    for (int np = 0; np < 2; np++){
      ldm_x4t(bh[np], sb + OXH + boff + np*32);
      ldm_x4t(bl[np], sb + OXL + boff + np*32);
    }
    {
      uint32_t fh[2][4], fl[2][4];
      #pragma unroll
      for (int mi = 0; mi < 2; mi++){
        ldm_x4(fh[mi], sb + OAH + aoff + (uint32_t)mi*16*48);
        ldm_x4(fl[mi], sb + OAL + aoff + (uint32_t)mi*16*48);
      }
      #pragma unroll
      for (int mi = 0; mi < 2; mi++){
        #pragma unroll
        for (int nn = 0; nn < 4; nn++){
          int np = nn >> 1, sub = (nn & 1) * 2;
          mma_bf16(acc1[mi][nn], fh[mi], bh[np][sub], bh[np][sub+1]);
          mma_bf16(acc1[mi][nn], fh[mi], bl[np][sub], bl[np][sub+1]);
          mma_bf16(acc1[mi][nn], fl[mi], bh[np][sub], bh[np][sub+1]);
        }
      }
    }
    {
      uint32_t fh[2][4], fl[2][4];
      #pragma unroll
      for (int mi = 0; mi < 2; mi++){
        ldm_x4(fh[mi], sb + OMH + aoff + (uint32_t)mi*16*48);
        ldm_x4(fl[mi], sb + OML + aoff + (uint32_t)mi*16*48);
      }
      #pragma unroll
      for (int mi = 0; mi < 2; mi++){
        #pragma unroll
        for (int nn = 0; nn < 4; nn++){
          int np = nn >> 1, sub = (nn & 1) * 2;
          mma_bf16(acc2[mi][nn], fh[mi], bh[np][sub], bh[np][sub+1]);
          mma_bf16(acc2[mi][nn], fh[mi], bl[np][sub], bl[np][sub+1]);
          mma_bf16(acc2[mi][nn], fl[mi], bh[np][sub], bh[np][sub+1]);
        }
      }
    }
    __syncthreads();
  }

  int rbase = m0 + warp_m*32 + (lane >> 2);
  int cbase = warp_n*32 + (lane & 3)*2;
  #pragma unroll
  for (int mi = 0; mi < 2; mi++){
    #pragma unroll
    for (int nn = 0; nn < 4; nn++){
      int col = cbase + nn*8;
      #pragma unroll
      for (int half = 0; half < 2; half++){
        int row = rbase + mi*16 + half*8;
        size_t off = ((size_t)bt*512 + row)*64 + col;
        float v0 = acc1[mi][nn][half*2], v1 = acc1[mi][nn][half*2+1];
        __nv_bfloat16 h0,l0,h1,l1;
        split_bf16(v0,h0,l0); split_bf16(v1,h1,l1);
        __nv_bfloat162 hv; hv.x=h0; hv.y=h1;
        __nv_bfloat162 lv; lv.x=l0; lv.y=l1;
        *(__nv_bfloat162*)(g_y1h + off) = hv;
        *(__nv_bfloat162*)(g_y1l + off) = lv;
        float2 z = *(const float2*)(Z + off);
        float w0 = acc2[mi][nn][half*2] - z.x;
        float w1 = acc2[mi][nn][half*2+1] - z.y;
        split_bf16(w0,h0,l0); split_bf16(w1,h1,l1);
        hv.x=h0; hv.y=h1; lv.x=l0; lv.y=l1;
        *(__nv_bfloat162*)(g_y2h + off) = hv;
        *(__nv_bfloat162*)(g_y2l + off) = lv;
      }
    }
  }
}

// ---------------- 7) HMMA combine GEMM: act([Y0|Y1|Y2] @ W[bt] + b) ----------------
template<int WHICH>
__global__ void __launch_bounds__(256, 2) k_combT(){
  constexpr int No = WHICH ? 64 : 128;
  const __nv_bfloat16* __restrict__ Y0h = WHICH ? g_yzh : g_deh;
  const __nv_bfloat16* __restrict__ Y0l = WHICH ? g_yzl : g_del;
  const __nv_bfloat16* __restrict__ Wh  = WHICH ? g_Wuh : g_W1h;
  const __nv_bfloat16* __restrict__ Wl  = WHICH ? g_Wul : g_W1l;

  __shared__ __nv_bfloat16 sAh[2][128*24], sAl[2][128*24];
  __shared__ __nv_bfloat16 sXh[2][16*72],  sXl[2][16*72];

  int bt = blockIdx.z, n0 = blockIdx.y * 128, ct = blockIdx.x;
  int tid = threadIdx.x, wid = tid >> 5, lane = tid & 31;
  int warp_m = wid >> 1, warp_n = wid & 1;

  uint32_t uAh[2] = { s2u(sAh[0]), s2u(sAh[1]) };
  uint32_t uAl[2] = { s2u(sAl[0]), s2u(sAl[1]) };
  uint32_t uXh[2] = { s2u(sXh[0]), s2u(sXh[1]) };
  uint32_t uXl[2] = { s2u(sXl[0]), s2u(sXl[1]) };

  int arow = tid >> 1, aq = tid & 1;
  int xr = (tid & 127) >> 3, xq = tid & 7;
  bool xhi = tid < 128;

  auto load_chunk = [&](int c, int buf){
    int seg = c >> 2, kin0 = (c & 3) * 16;
    const __nv_bfloat16* Yh = seg==0 ? Y0h : seg==1 ? g_y1h : g_y2h;
    const __nv_bfloat16* Yl = seg==0 ? Y0l : seg==1 ? g_y1l : g_y2l;
    size_t ga = ((size_t)bt*512 + n0 + arow)*64 + kin0 + aq*8;
    cp16(uAh[buf] + arow*48 + aq*16, Yh + ga);
    cp16(uAl[buf] + arow*48 + aq*16, Yl + ga);
    size_t gw = (((size_t)bt*3 + seg)*64 + kin0 + xr)*No + ct*64 + xq*8;
    if (xhi) cp16(uXh[buf] + xr*144 + xq*16, Wh + gw);
    else     cp16(uXl[buf] + xr*144 + xq*16, Wl + gw);
  };

  float acc[2][4][4];
  #pragma unroll
  for (int mi=0;mi<2;mi++)
    #pragma unroll
    for (int nn=0;nn<4;nn++)
      #pragma unroll
      for (int j=0;j<4;j++) acc[mi][nn][j] = 0.f;

  load_chunk(0, 0);
  asm volatile("cp.async.commit_group;" ::: "memory");

  uint32_t lrow = lane & 15;
  uint32_t lk = (lane >> 4) << 4;

  for (int c = 0; c < 12; c++){
    int buf = c & 1;
    if (c < 11){
      load_chunk(c + 1, buf ^ 1);
      asm volatile("cp.async.commit_group;" ::: "memory");
      asm volatile("cp.async.wait_group 1;" ::: "memory");
    } else {
      asm volatile("cp.async.wait_group 0;" ::: "memory");
    }
    __syncthreads();

    uint32_t ah[2][4], al[2][4], bh[2][4], bl[2][4];
    #pragma unroll
    for (int mi = 0; mi < 2; mi++){
      uint32_t aoff = (uint32_t)(warp_m*32 + mi*16 + lrow)*48 + lk;
      ldm_x4(ah[mi], uAh[buf] + aoff);
      ldm_x4(al[mi], uAl[buf] + aoff);
    }
    #pragma unroll
    for (int np = 0; np < 2; np++){
      uint32_t boff = lrow*144 + (uint32_t)(warp_n*32 + np*16)*2 + lk;
      ldm_x4t(bh[np], uXh[buf] + boff);
      ldm_x4t(bl[np], uXl[buf] + boff);
    }
    #pragma unroll
    for (int mi = 0; mi < 2; mi++){
      #pragma unroll
      for (int nn = 0; nn < 4; nn++){
        int np = nn >> 1, sub = (nn & 1) * 2;
        mma_bf16(acc[mi][nn], ah[mi], bh[np][sub], bh[np][sub+1]);
        mma_bf16(acc[mi][nn], ah[mi], bl[np][sub], bl[np][sub+1]);
        mma_bf16(acc[mi][nn], al[mi], bh[np][sub], bh[np][sub+1]);
      }
    }
    __syncthreads();
  }

  int rbase = n0 + warp_m*32 + (lane >> 2);
  int cbase = warp_n*32 + (lane & 3)*2;
  #pragma unroll
  for (int mi = 0; mi < 2; mi++){
    #pragma unroll
    for (int nn = 0; nn < 4; nn++){
      int col = cbase + nn*8;
      int gcol = ct*64 + col;
      #pragma unroll
      for (int half = 0; half < 2; half++){
        int row = rbase + mi*16 + half*8;
        size_t off = ((size_t)bt*512 + row)*64 + col;
        float v0 = acc[mi][nn][half*2], v1 = acc[mi][nn][half*2+1];
        if (WHICH == 0){
          v0 += g_b1[(size_t)bt*128 + gcol];
          v1 += g_b1[(size_t)bt*128 + gcol + 1];
          v0 = 1.f/(1.f + __expf(-v0));
          v1 = 1.f/(1.f + __expf(-v1));
          if (ct == 0){
            float2 de = *(const float2*)(g_de + off);
            float z0 = v0 * de.x, z1 = v1 * de.y;
            *(float2*)(g_yz + off) = make_float2(z0, z1);
            __nv_bfloat16 h0,l0,h1,l1;
            split_bf16(z0,h0,l0); split_bf16(z1,h1,l1);
            __nv_bfloat162 hv; hv.x=h0; hv.y=h1;
            __nv_bfloat162 lv; lv.x=l0; lv.y=l1;
            *(__nv_bfloat162*)(g_yzh + off) = hv;
            *(__nv_bfloat162*)(g_yzl + off) = lv;
          } else {
            *(float2*)(g_rg + off) = make_float2(v0, v1);
          }
        } else {
          v0 = tanhf(v0 + g_bu[(size_t)bt*64 + gcol]);
          v1 = tanhf(v1 + g_bu[(size_t)bt*64 + gcol + 1]);
          *(float2*)(g_hc + off) = make_float2(v0, v1);
        }
      }
    }
  }
}

// ---------------- 8) final projection ----------------
__global__ void k_out(const float* __restrict__ outw, const float* __restrict__ outb,
                      float* __restrict__ out){
  int gw = blockIdx.x*8 + (threadIdx.x >> 5);
  int lane = threadIdx.x & 31;
  size_t mn = (size_t)gw;
  int m = gw >> 9;
  int t = m % 12;
  size_t base = mn << 6;
  float s = 0.f;
  #pragma unroll
  for (int ii = 0; ii < 2; ii++){
    int i = lane + ii*32;
    float rg = g_rg[base + i];
    float de = g_de[base + i];
    float hc = g_hc[base + i];
    float st = fmaf(rg, de - hc, hc);
    s = fmaf(st, outw[t*64 + i], s);
  }
  #pragma unroll
  for (int off = 16; off > 0; off >>= 1) s += __shfl_xor_sync(0xffffffffu, s, off);
  if (lane == 0) out[mn] = s + outb[t];
}

// ---------------- launch ----------------
extern "C" void kernel_launch(void* const* d_in, const int* in_sizes, int n_in,
                              void* d_out, int out_size){
  (void)in_sizes; (void)n_in; (void)out_size;
  const float* hn  = (const float*)d_in[2];
  const float* ne1 = (const float*)d_in[3];
  const float* ne2 = (const float*)d_in[4];
  const float* E   = (const float*)d_in[5];
  const float* Wq  = (const float*)d_in[6];
  const float* bq  = (const float*)d_in[7];
  const float* Wk  = (const float*)d_in[8];
  const float* bk  = (const float*)d_in[9];
  const float* Wv  = (const float*)d_in[10];
  const float* bv  = (const float*)d_in[11];
  const float* taw = (const float*)d_in[12];
  const float* tab = (const float*)d_in[13];
  const float* gwp = (const float*)d_in[14];
  const float* gw  = (const float*)d_in[15];
  const float* gbp = (const float*)d_in[16];
  const float* gb  = (const float*)d_in[17];
  const float* uwp = (const float*)d_in[18];
  const float* uw  = (const float*)d_in[19];
  const float* ubp = (const float*)d_in[20];
  const float* ub  = (const float*)d_in[21];
  const float* outw= (const float*)d_in[22];
  const float* outb= (const float*)d_in[23];
  float* out = (float*)d_out;

  cudaFuncSetAttribute(k_bmma2, cudaFuncAttributeMaxDynamicSharedMemorySize, SMB);

  k_adj<<<512, 512>>>(E);
  k_a2<<<dim3(4, 8), 128>>>();
  k_prep<<<896, 64>>>(ne1, ne2, Wq, bq, Wk, bk, Wv, bv);
  k_qkvu<<<dim3(4, 512), 256>>>(hn, Wq, Wk, Wv, taw, tab);
  k_attn2<<<4096, 256>>>(taw);
  k_wgen<<<dim3(390, 12), 256>>>(ne2, gwp, gw, 24960, 0);
  k_wgen<<<dim3(195, 12), 256>>>(ne2, uwp, uw, 12480, 1);
  k_wgen<<<dim3(2, 12), 256>>>(ne2, gbp, gb, 128, 2);
  k_wgen<<<dim3(1, 12), 256>>>(ne2, ubp, ub, 64, 3);
  k_bmma2<<<dim3(4, 768), 256, SMB>>>(0);        // y1 = A@de, y2 = M2@de - de
  k_combT<0><<<dim3(2, 4, 768), 256>>>();        // yz / rg
  k_bmma2<<<dim3(4, 768), 256, SMB>>>(1);        // y1 = A@yz, y2 = M2@yz - yz
  k_combT<1><<<dim3(1, 4, 768), 256>>>();        // hc
  k_out<<<49152, 256>>>(outw, outb, out);
}

// round 7
// speedup vs baseline: 2.1619x; 1.0870x over previous
#include <cuda_runtime.h>
#include <cuda_bf16.h>
#include <math.h>
#include <stdint.h>

// B=64, T=12, N=512, H=64, TD=32, ED=16, CHEB_K=3, D_HEADS=8, M=768
constexpr size_t NF = (size_t)768*512*64;

// ---------------- device scratch ----------------
__device__ float g_Af[512*512];
__device__ __nv_bfloat16 g_Ah[512*512], g_Al[512*512];
__device__ __nv_bfloat16 g_M2h[512*512], g_M2l[512*512];
__device__ float g_de[NF], g_yz[NF], g_hc[NF], g_rg[NF];
__device__ __nv_bfloat16 g_deh[NF], g_del[NF], g_y1h[NF], g_y1l[NF];
__device__ __nv_bfloat16 g_y2h[NF], g_y2l[NF], g_yzh[NF], g_yzl[NF];
__device__ __nv_bfloat16 g_W1h[(size_t)768*3*64*128], g_W1l[(size_t)768*3*64*128];
__device__ __nv_bfloat16 g_Wuh[(size_t)768*3*64*64],  g_Wul[(size_t)768*3*64*64];
__device__ float g_b1[768*128], g_bu[768*64];

// ---------------- ptx helpers (sm_80+ baseline only) ----------------
__device__ __forceinline__ uint32_t s2u(const void* p){
  uint32_t a;
  asm("{ .reg .u64 t; cvta.to.shared.u64 t, %1; cvt.u32.u64 %0, t; }" : "=r"(a) : "l"(p));
  return a;
}
__device__ __forceinline__ void cp16(uint32_t dst, const void* src){
  asm volatile("cp.async.cg.shared.global [%0], [%1], 16;" :: "r"(dst), "l"(src) : "memory");
}
__device__ __forceinline__ void ldm_x4(uint32_t* r, uint32_t addr){
  asm volatile("ldmatrix.sync.aligned.m8n8.x4.shared.b16 {%0,%1,%2,%3}, [%4];"
    : "=r"(r[0]), "=r"(r[1]), "=r"(r[2]), "=r"(r[3]) : "r"(addr));
}
__device__ __forceinline__ void ldm_x4t(uint32_t* r, uint32_t addr){
  asm volatile("ldmatrix.sync.aligned.m8n8.x4.trans.shared.b16 {%0,%1,%2,%3}, [%4];"
    : "=r"(r[0]), "=r"(r[1]), "=r"(r[2]), "=r"(r[3]) : "r"(addr));
}
__device__ __forceinline__ void mma_bf16(float* c, const uint32_t* a, uint32_t b0, uint32_t b1){
  asm volatile(
    "mma.sync.aligned.m16n8k16.row.col.f32.bf16.bf16.f32 "
    "{%0,%1,%2,%3}, {%4,%5,%6,%7}, {%8,%9}, {%0,%1,%2,%3};"
    : "+f"(c[0]), "+f"(c[1]), "+f"(c[2]), "+f"(c[3])
    : "r"(a[0]), "r"(a[1]), "r"(a[2]), "r"(a[3]), "r"(b0), "r"(b1));
}
__device__ __forceinline__ void split_bf16(float f, __nv_bfloat16& h, __nv_bfloat16& l){
  h = __float2bfloat16(f);
  l = __float2bfloat16(f - __bfloat162float(h));
}

// ---------------- 1) adjacency (fp32 + bf16 hi/lo) ----------------
__global__ void k_adj(const float* __restrict__ E){
  int i = blockIdx.x, j = threadIdx.x;
  __shared__ float Ei[16];
  __shared__ float red[512];
  if (j < 16) Ei[j] = E[i*16 + j];
  __syncthreads();
  float d = 0.f;
  #pragma unroll
  for (int c = 0; c < 16; c++) d = fmaf(Ei[c], E[j*16 + c], d);
  d = fmaxf(d, 0.f);
  red[j] = d; __syncthreads();
  for (int s = 256; s > 0; s >>= 1){ if (j < s) red[j] = fmaxf(red[j], red[j+s]); __syncthreads(); }
  float mx = red[0];
  __syncthreads();
  float e = __expf(d - mx);
  red[j] = e; __syncthreads();
  for (int s = 256; s > 0; s >>= 1){ if (j < s) red[j] += red[j+s]; __syncthreads(); }
  float a = e * (1.f / red[0]);
  g_Af[i*512 + j] = a;
  __nv_bfloat16 h, l; split_bf16(a, h, l);
  g_Ah[i*512 + j] = h; g_Al[i*512 + j] = l;
}

// ---------------- 1b) M2 = 2*A@A -> bf16 hi/lo ----------------
__global__ void k_a2(){
  int row0 = blockIdx.x * 128, col0 = blockIdx.y * 64;
  __shared__ float As[128][17];
  __shared__ __align__(16) float Bs[16][64];
  int tid = threadIdx.x;
  int tx = tid & 7, ty = tid >> 3;
  float acc[8][8];
  #pragma unroll
  for (int i=0;i<8;i++)
    #pragma unroll
    for (int j=0;j<8;j++) acc[i][j] = 0.f;
  for (int k0 = 0; k0 < 512; k0 += 16){
    #pragma unroll
    for (int i = 0; i < 4; i++){
      int idx = tid + i*128;
      int r = idx >> 2, kq = idx & 3;
      float4 a4 = *(const float4*)(g_Af + (size_t)(row0 + r)*512 + k0 + kq*4);
      As[r][kq*4+0]=a4.x; As[r][kq*4+1]=a4.y; As[r][kq*4+2]=a4.z; As[r][kq*4+3]=a4.w;
    }
    #pragma unroll
    for (int i = 0; i < 2; i++){
      int idx = tid + i*128;
      int r = idx >> 4, cq = idx & 15;
      float4 b4 = *(const float4*)(g_Af + (size_t)(k0 + r)*512 + col0 + cq*4);
      *(float4*)&Bs[r][cq*4] = b4;
    }
    __syncthreads();
    #pragma unroll
    for (int k = 0; k < 16; k++){
      float a[8], b[8];
      #pragma unroll
      for (int i=0;i<8;i++) a[i] = As[ty*8+i][k];
      float4 b0 = *(const float4*)&Bs[k][tx*8];
      float4 b1 = *(const float4*)&Bs[k][tx*8+4];
      b[0]=b0.x; b[1]=b0.y; b[2]=b0.z; b[3]=b0.w;
      b[4]=b1.x; b[5]=b1.y; b[6]=b1.z; b[7]=b1.w;
      #pragma unroll
      for (int i=0;i<8;i++)
        #pragma unroll
        for (int j=0;j<8;j++) acc[i][j] = fmaf(a[i], b[j], acc[i][j]);
    }
    __syncthreads();
  }
  #pragma unroll
  for (int i=0;i<8;i++){
    size_t r = row0 + ty*8 + i;
    #pragma unroll
    for (int j=0;j<8;j++){
      float v = 2.f * acc[i][j];
      __nv_bfloat16 h, l; split_bf16(v, h, l);
      g_M2h[r*512 + col0 + tx*8 + j] = h;
      g_M2l[r*512 + col0 + tx*8 + j] = l;
    }
  }
}

// ---------------- 2) fused prep + qkvu + attention -> de (fp32 + bf16 hi/lo) ----------------
// one CTA = 64 consecutive (b,n) rows (same b). Dynamic smem layout (floats):
constexpr int QA_OX  = 0;       // X  [64][68]
constexpr int QA_OB  = 4352;    // W / tw [64][68]
constexpr int QA_OQ  = 8704;    // qkvu [64][260]
constexpr int QA_OPQ = 25344;   // pq [12][64]
constexpr int QA_OPK = 26112;   // pk [64]
constexpr int QA_OPV = 26176;   // pv [64]
constexpr int QA_OES = 26240;   // es [8 warps][96]
constexpr int QA_SMB = 27008 * 4;

__global__ void __launch_bounds__(256, 2) k_qa(
    const float* __restrict__ hn, const float* __restrict__ ne1, const float* __restrict__ ne2,
    const float* __restrict__ Wq, const float* __restrict__ bq,
    const float* __restrict__ Wk, const float* __restrict__ bk,
    const float* __restrict__ Wv, const float* __restrict__ bv,
    const float* __restrict__ taw, const float* __restrict__ tab){
  extern __shared__ float sm[];
  float* Xs = sm + QA_OX;
  float* Bs = sm + QA_OB;
  float* Q  = sm + QA_OQ;
  float* pq = sm + QA_OPQ;
  float* pk = sm + QA_OPK;
  float* pv = sm + QA_OPV;
  float* es = sm + QA_OES;
  int tid = threadIdx.x;
  int bn0 = blockIdx.x * 64;
  int b = bn0 >> 9;

  // X rows
  #pragma unroll
  for (int i = tid; i < 64*16; i += 256){
    int r = i >> 4, q = i & 15;
    float4 v = *(const float4*)(hn + (size_t)(bn0 + r)*64 + q*4);
    Xs[r*68 + q*4+0]=v.x; Xs[r*68 + q*4+1]=v.y; Xs[r*68 + q*4+2]=v.z; Xs[r*68 + q*4+3]=v.w;
  }
  // pk / pv
  const float* e1 = ne1 + (size_t)(b*12 + 11)*32;
  if (tid < 64){
    float a = bk[tid];
    #pragma unroll
    for (int d = 0; d < 32; d++) a = fmaf(e1[d], Wk[d*64 + tid], a);
    pk[tid] = a;
  } else if (tid < 128){
    int o = tid - 64;
    float a = bv[o];
    #pragma unroll
    for (int d = 0; d < 32; d++) a = fmaf(e1[d], Wv[d*64 + o], a);
    pv[o] = a;
  }
  // pq (12 x 64)
  for (int i = tid; i < 768; i += 256){
    int t = i >> 6, o = i & 63;
    const float* e2 = ne2 + (size_t)(b*12 + t)*32;
    float a = bq[o];
    #pragma unroll
    for (int d = 0; d < 32; d++) a = fmaf(e2[d], Wq[d*64 + o], a);
    pq[t*64 + o] = a;
  }
  __syncthreads();

  int ty = tid >> 4, tx = tid & 15;
  for (int mode = 0; mode < 4; mode++){
    const float* Wsrc = (mode==0) ? Wq + 2048 : (mode==1) ? Wk + 2048
                      : (mode==2) ? Wv + 2048 : taw;
    #pragma unroll
    for (int i = tid; i < 64*16; i += 256){
      int r = i >> 4, q = i & 15;
      float4 w4 = *(const float4*)(Wsrc + (size_t)r*64 + q*4);
      Bs[r*68 + q*4+0]=w4.x; Bs[r*68 + q*4+1]=w4.y; Bs[r*68 + q*4+2]=w4.z; Bs[r*68 + q*4+3]=w4.w;
    }
    __syncthreads();
    float acc[4][4];
    #pragma unroll
    for (int i=0;i<4;i++){ acc[i][0]=0.f; acc[i][1]=0.f; acc[i][2]=0.f; acc[i][3]=0.f; }
    #pragma unroll 16
    for (int k = 0; k < 64; k++){
      float a[4], bb[4];
      #pragma unroll
      for (int i=0;i<4;i++) a[i] = Xs[(ty*4+i)*68 + k];
      #pragma unroll
      for (int j=0;j<4;j++) bb[j] = Bs[k*68 + tx*4+j];
      #pragma unroll
      for (int i=0;i<4;i++)
        #pragma unroll
        for (int j=0;j<4;j++) acc[i][j] = fmaf(a[i], bb[j], acc[i][j]);
    }
    #pragma unroll
    for (int i=0;i<4;i++){
      int r = ty*4 + i;
      #pragma unroll
      for (int j=0;j<4;j++){
        int c = tx*4 + j;
        float v = acc[i][j];
        if (mode == 1)      v = fmaxf(v + pk[c], 0.f);
        else if (mode == 2) v = fmaxf(v + pv[c], 0.f);
        else if (mode == 3) v = v + tab[c];
        Q[r*260 + mode*64 + c] = v;
      }
    }
    __syncthreads();
  }
  // tw = ta_w[1] into Bs
  for (int i = tid; i < 4096; i += 256) Bs[(i>>6)*68 + (i&63)] = taw[4096 + i];
  __syncthreads();

  // attention: warp w handles local rows w*8 .. w*8+7
  int w = tid >> 5, lane = tid & 31;
  float* esw = es + w*96;
  int c0 = lane*2;
  for (int i = 0; i < 8; i++){
    int lr = w*8 + i;
    int n = (bn0 + lr) & 511;
    const float* q_ = Q + lr*260;
    float u0 = q_[192+c0], u1 = q_[193+c0];
    float vw0[8], vw1[8];
    #pragma unroll
    for (int d = 0; d < 8; d++){
      float a0 = 0.f, a1 = 0.f;
      #pragma unroll
      for (int cp = 0; cp < 8; cp++){
        float vv = q_[128 + d*8 + cp];
        float2 t2 = *(const float2*)&Bs[(d*8+cp)*68 + c0];
        a0 = fmaf(vv, t2.x, a0); a1 = fmaf(vv, t2.y, a1);
      }
      vw0[d] = a0; vw1[d] = a1;
    }
    for (int task = lane; task < 96; task += 32){
      int d = task / 12, t = task - d*12;
      const float* pqd = pq + t*64 + d*8;
      float e = 0.f;
      #pragma unroll
      for (int cp = 0; cp < 8; cp++){
        float qv = fmaxf(q_[d*8+cp] + pqd[cp], 0.f);
        e = fmaf(qv, q_[64 + d*8 + cp], e);
      }
      esw[d*12 + t] = e;
    }
    __syncwarp();
    if (lane < 8){
      float mx = -1e30f;
      #pragma unroll
      for (int t=0;t<12;t++) mx = fmaxf(mx, esw[lane*12 + t]);
      float ssum = 0.f;
      #pragma unroll
      for (int t=0;t<12;t++){ float ex = __expf(esw[lane*12+t]-mx); esw[lane*12+t]=ex; ssum+=ex; }
      float inv = 1.f/ssum;
      #pragma unroll
      for (int t=0;t<12;t++) esw[lane*12+t] *= inv;
    }
    __syncwarp();
    #pragma unroll
    for (int t = 0; t < 12; t++){
      float o0 = u0, o1 = u1;
      #pragma unroll
      for (int d = 0; d < 8; d++){
        float a = esw[d*12 + t];
        o0 = fmaf(a, vw0[d], o0); o1 = fmaf(a, vw1[d], o1);
      }
      size_t off = ((size_t)(b*12 + t)*512 + n)*64;
      *(float2*)(g_de + off + c0) = make_float2(o0, o1);
      __nv_bfloat16 h0,l0,h1,l1;
      split_bf16(o0,h0,l0); split_bf16(o1,h1,l1);
      __nv_bfloat162 hv; hv.x=h0; hv.y=h1;
      __nv_bfloat162 lv; lv.x=l0; lv.y=l1;
      *(__nv_bfloat162*)(g_deh + off + c0) = hv;
      *(__nv_bfloat162*)(g_del + off + c0) = lv;
    }
    __syncwarp();
  }
}

// ---------------- 3) weight gen ----------------
__global__ void k_wgen(const float* __restrict__ Am, const float* __restrict__ Bw,
                       const float* __restrict__ g, int Nc, int dst){
  int col0 = blockIdx.x * 64, row0 = blockIdx.y * 64;
  __shared__ float As[64][33];
  __shared__ float Bs[32][65];
  int tid = threadIdx.x;
  #pragma unroll
  for (int i = 0; i < 2; i++){
    int idx = tid + i*256;
    { int r = idx >> 3, kq = idx & 7;
      float4 a4 = *(const float4*)(Am + (size_t)(row0 + r)*32 + kq*4);
      As[r][kq*4+0]=a4.x; As[r][kq*4+1]=a4.y; As[r][kq*4+2]=a4.z; As[r][kq*4+3]=a4.w; }
    { int r = idx >> 4, cq = idx & 15;
      float4 b4 = *(const float4*)(Bw + (size_t)r*Nc + col0 + cq*4);
      Bs[r][cq*4+0]=b4.x; Bs[r][cq*4+1]=b4.y; Bs[r][cq*4+2]=b4.z; Bs[r][cq*4+3]=b4.w; }
  }
  __syncthreads();
  int ty = tid >> 4, tx = tid & 15;
  float acc[4][4];
  #pragma unroll
  for (int i=0;i<4;i++){ acc[i][0]=0.f; acc[i][1]=0.f; acc[i][2]=0.f; acc[i][3]=0.f; }
  #pragma unroll
  for (int k = 0; k < 32; k++){
    float a[4], b[4];
    #pragma unroll
    for (int i=0;i<4;i++) a[i] = As[ty*4+i][k];
    #pragma unroll
    for (int j=0;j<4;j++) b[j] = Bs[k][tx*4+j];
    #pragma unroll
    for (int i=0;i<4;i++)
      #pragma unroll
      for (int j=0;j<4;j++) acc[i][j] = fmaf(a[i], b[j], acc[i][j]);
  }
  int No = (dst==0) ? 128 : 64;
  int GNo = 65*No;
  #pragma unroll
  for (int i=0;i<4;i++){
    int r = row0 + ty*4 + i;
    #pragma unroll
    for (int j=0;j<4;j++){
      int c = col0 + tx*4 + j;
      float v = acc[i][j] + g[c];
      if (dst == 2)      g_b1[(size_t)r*128 + c] = v;
      else if (dst == 3) g_bu[(size_t)r*64 + c] = v;
      else {
        int seg = c / GNo, rem = c - seg*GNo;
        int ki = rem / No, o = rem - ki*No;
        if (ki >= 1){
          size_t off = (((size_t)r*3 + seg)*64 + (ki-1))*No + o;
          __nv_bfloat16 h, l; split_bf16(v, h, l);
          if (dst == 0){ g_W1h[off] = h; g_W1l[off] = l; }
          else         { g_Wuh[off] = h; g_Wul[off] = l; }
        }
      }
    }
  }
}

// ---------------- 4) dual HMMA: y1 = A@X, y2 = M2@X - X (bf16 hi/lo, 3-term, 3-stage) ----------------
constexpr int STG_SZ = 29184;
constexpr int OAH = 0, OAL = 6144, OMH = 12288, OML = 18432, OXH = 24576, OXL = 26880;
constexpr int SMB = 3 * STG_SZ;   // 87552

__global__ void __launch_bounds__(256, 2) k_bmma2(int from_yz){
  extern __shared__ __align__(16) char dyn[];
  uint32_t sb = s2u(dyn);
  const __nv_bfloat16* __restrict__ Xh = from_yz ? g_yzh : g_deh;
  const __nv_bfloat16* __restrict__ Xl = from_yz ? g_yzl : g_del;
  const float* __restrict__ Z = from_yz ? g_yz : g_de;

  int bt = blockIdx.y, m0 = blockIdx.x * 128;
  int tid = threadIdx.x, wid = tid >> 5, lane = tid & 31;
  int warp_m = wid >> 1, warp_n = wid & 1;

  int arow = tid >> 1, aq = tid & 1;
  int xr = (tid & 127) >> 3, xq = tid & 7;
  bool xhi = tid < 128;

  auto load_chunk = [&](int c, int st){
    uint32_t base = sb + (uint32_t)st * STG_SZ;
    int k0 = c * 16;
    size_t ga = (size_t)(m0 + arow)*512 + k0 + aq*8;
    uint32_t so = arow*48 + aq*16;
    cp16(base + OAH + so, g_Ah + ga);
    cp16(base + OAL + so, g_Al + ga);
    cp16(base + OMH + so, g_M2h + ga);
    cp16(base + OML + so, g_M2l + ga);
    size_t gx = ((size_t)bt*512 + k0 + xr)*64 + xq*8;
    uint32_t xo = xr*144 + xq*16;
    if (xhi) cp16(base + OXH + xo, Xh + gx);
    else     cp16(base + OXL + xo, Xl + gx);
  };

  float acc1[2][4][4], acc2[2][4][4];
  #pragma unroll
  for (int mi=0;mi<2;mi++)
    #pragma unroll
    for (int nn=0;nn<4;nn++)
      #pragma unroll
      for (int j=0;j<4;j++){ acc1[mi][nn][j] = 0.f; acc2[mi][nn][j] = 0.f; }

  load_chunk(0, 0);
  asm volatile("cp.async.commit_group;" ::: "memory");
  load_chunk(1, 1);
  asm volatile("cp.async.commit_group;" ::: "memory");

  uint32_t lrow = lane & 15;
  uint32_t lk = (lane >> 4) << 4;

  for (int c = 0; c < 32; c++){
    if (c < 31) asm volatile("cp.async.wait_group 1;" ::: "memory");
    else        asm volatile("cp.async.wait_group 0;" ::: "memory");
    __syncthreads();

    int st = c % 3;
    uint32_t base = sb + (uint32_t)st * STG_SZ;
    uint32_t aoff = (uint32_t)(warp_m*32 + lrow)*48 + lk;
    uint32_t boff = lrow*144 + (uint32_t)warp_n*64 + lk;

    uint32_t bh[2][4], bl[2][4];
    #pragma unroll
    for (int np = 0; np < 2; np++){
      ldm_x4t(bh[np], base + OXH + boff + np*32);
      ldm_x4t(bl[np], base + OXL + boff + np*32);
    }
    {
      uint32_t fh[2][4], fl[2][4];
      #pragma unroll
      for (int mi = 0; mi < 2; mi++){
        ldm_x4(fh[mi], base + OAH + aoff + (uint32_t)mi*768);
        ldm_x4(fl[mi], base + OAL + aoff + (uint32_t)mi*768);
      }
      #pragma unroll
      for (int mi = 0; mi < 2; mi++){
        #pragma unroll
        for (int nn = 0; nn < 4; nn++){
          int np = nn >> 1, sub = (nn & 1) * 2;
          mma_bf16(acc1[mi][nn], fh[mi], bh[np][sub], bh[np][sub+1]);
          mma_bf16(acc1[mi][nn], fh[mi], bl[np][sub], bl[np][sub+1]);
          mma_bf16(acc1[mi][nn], fl[mi], bh[np][sub], bh[np][sub+1]);
        }
      }
    }
    {
      uint32_t fh[2][4], fl[2][4];
      #pragma unroll
      for (int mi = 0; mi < 2; mi++){
        ldm_x4(fh[mi], base + OMH + aoff + (uint32_t)mi*768);
        ldm_x4(fl[mi], base + OML + aoff + (uint32_t)mi*768);
      }
      #pragma unroll
      for (int mi = 0; mi < 2; mi++){
        #pragma unroll
        for (int nn = 0; nn < 4; nn++){
          int np = nn >> 1, sub = (nn & 1) * 2;
          mma_bf16(acc2[mi][nn], fh[mi], bh[np][sub], bh[np][sub+1]);
          mma_bf16(acc2[mi][nn], fh[mi], bl[np][sub], bl[np][sub+1]);
          mma_bf16(acc2[mi][nn], fl[mi], bh[np][sub], bh[np][sub+1]);
        }
      }
    }
    if (c + 2 < 32){
      load_chunk(c + 2, (c + 2) % 3);
      asm volatile("cp.async.commit_group;" ::: "memory");
    }
  }

  int rbase = m0 + warp_m*32 + (lane >> 2);
  int cbase = warp_n*32 + (lane & 3)*2;
  #pragma unroll
  for (int mi = 0; mi < 2; mi++){
    #pragma unroll
    for (int nn = 0; nn < 4; nn++){
      int col = cbase + nn*8;
      #pragma unroll
      for (int half = 0; half < 2; half++){
        int row = rbase + mi*16 + half*8;
        size_t off = ((size_t)bt*512 + row)*64 + col;
        float v0 = acc1[mi][nn][half*2], v1 = acc1[mi][nn][half*2+1];
        __nv_bfloat16 h0,l0,h1,l1;
        split_bf16(v0,h0,l0); split_bf16(v1,h1,l1);
        __nv_bfloat162 hv; hv.x=h0; hv.y=h1;
        __nv_bfloat162 lv; lv.x=l0; lv.y=l1;
        *(__nv_bfloat162*)(g_y1h + off) = hv;
        *(__nv_bfloat162*)(g_y1l + off) = lv;
        float2 z = *(const float2*)(Z + off);
        float w0 = acc2[mi][nn][half*2] - z.x;
        float w1 = acc2[mi][nn][half*2+1] - z.y;
        split_bf16(w0,h0,l0); split_bf16(w1,h1,l1);
        hv.x=h0; hv.y=h1; lv.x=l0; lv.y=l1;
        *(__nv_bfloat162*)(g_y2h + off) = hv;
        *(__nv_bfloat162*)(g_y2l + off) = lv;
      }
    }
  }
}

// ---------------- 5) HMMA combine GEMM: act([Y0|Y1|Y2] @ W[bt] + b) ----------------
template<int WHICH>
__global__ void __launch_bounds__(256, 2) k_combT(){
  constexpr int No = WHICH ? 64 : 128;
  const __nv_bfloat16* __restrict__ Y0h = WHICH ? g_yzh : g_deh;
  const __nv_bfloat16* __restrict__ Y0l = WHICH ? g_yzl : g_del;
  const __nv_bfloat16* __restrict__ Wh  = WHICH ? g_Wuh : g_W1h;
  const __nv_bfloat16* __restrict__ Wl  = WHICH ? g_Wul : g_W1l;

  __shared__ __nv_bfloat16 sAh[2][128*24], sAl[2][128*24];
  __shared__ __nv_bfloat16 sXh[2][16*72],  sXl[2][16*72];

  int bt = blockIdx.z, n0 = blockIdx.y * 128, ct = blockIdx.x;
  int tid = threadIdx.x, wid = tid >> 5, lane = tid & 31;
  int warp_m = wid >> 1, warp_n = wid & 1;

  uint32_t uAh[2] = { s2u(sAh[0]), s2u(sAh[1]) };
  uint32_t uAl[2] = { s2u(sAl[0]), s2u(sAl[1]) };
  uint32_t uXh[2] = { s2u(sXh[0]), s2u(sXh[1]) };
  uint32_t uXl[2] = { s2u(sXl[0]), s2u(sXl[1]) };

  int arow = tid >> 1, aq = tid & 1;
  int xr = (tid & 127) >> 3, xq = tid & 7;
  bool xhi = tid < 128;

  auto load_chunk = [&](int c, int buf){
    int seg = c >> 2, kin0 = (c & 3) * 16;
    const __nv_bfloat16* Yh = seg==0 ? Y0h : seg==1 ? g_y1h : g_y2h;
    const __nv_bfloat16* Yl = seg==0 ? Y0l : seg==1 ? g_y1l : g_y2l;
    size_t ga = ((size_t)bt*512 + n0 + arow)*64 + kin0 + aq*8;
    cp16(uAh[buf] + arow*48 + aq*16, Yh + ga);
    cp16(uAl[buf] + arow*48 + aq*16, Yl + ga);
    size_t gw = (((size_t)bt*3 + seg)*64 + kin0 + xr)*No + ct*64 + xq*8;
    if (xhi) cp16(uXh[buf] + xr*144 + xq*16, Wh + gw);
    else     cp16(uXl[buf] + xr*144 + xq*16, Wl + gw);
  };

  float acc[2][4][4];
  #pragma unroll
  for (int mi=0;mi<2;mi++)
    #pragma unroll
    for (int nn=0;nn<4;nn++)
      #pragma unroll
      for (int j=0;j<4;j++) acc[mi][nn][j] = 0.f;

  load_chunk(0, 0);
  asm volatile("cp.async.commit_group;" ::: "memory");

  uint32_t lrow = lane & 15;
  uint32_t lk = (lane >> 4) << 4;

  for (int c = 0; c < 12; c++){
    int buf = c & 1;
    if (c < 11){
      load_chunk(c + 1, buf ^ 1);
      asm volatile("cp.async.commit_group;" ::: "memory");
      asm volatile("cp.async.wait_group 1;" ::: "memory");
    } else {
      asm volatile("cp.async.wait_group 0;" ::: "memory");
    }
    __syncthreads();

    uint32_t ah[2][4], al[2][4], bh[2][4], bl[2][4];
    #pragma unroll
    for (int mi = 0; mi < 2; mi++){
      uint32_t aoff = (uint32_t)(warp_m*32 + mi*16 + lrow)*48 + lk;
      ldm_x4(ah[mi], uAh[buf] + aoff);
      ldm_x4(al[mi], uAl[buf] + aoff);
    }
    #pragma unroll
    for (int np = 0; np < 2; np++){
      uint32_t boff = lrow*144 + (uint32_t)(warp_n*32 + np*16)*2 + lk;
      ldm_x4t(bh[np], uXh[buf] + boff);
      ldm_x4t(bl[np], uXl[buf] + boff);
    }
    #pragma unroll
    for (int mi = 0; mi < 2; mi++){
      #pragma unroll
      for (int nn = 0; nn < 4; nn++){
        int np = nn >> 1, sub = (nn & 1) * 2;
        mma_bf16(acc[mi][nn], ah[mi], bh[np][sub], bh[np][sub+1]);
        mma_bf16(acc[mi][nn], ah[mi], bl[np][sub], bl[np][sub+1]);
        mma_bf16(acc[mi][nn], al[mi], bh[np][sub], bh[np][sub+1]);
      }
    }
    __syncthreads();
  }

  int rbase = n0 + warp_m*32 + (lane >> 2);
  int cbase = warp_n*32 + (lane & 3)*2;
  #pragma unroll
  for (int mi = 0; mi < 2; mi++){
    #pragma unroll
    for (int nn = 0; nn < 4; nn++){
      int col = cbase + nn*8;
      int gcol = ct*64 + col;
      #pragma unroll
      for (int half = 0; half < 2; half++){
        int row = rbase + mi*16 + half*8;
        size_t off = ((size_t)bt*512 + row)*64 + col;
        float v0 = acc[mi][nn][half*2], v1 = acc[mi][nn][half*2+1];
        if (WHICH == 0){
          v0 += g_b1[(size_t)bt*128 + gcol];
          v1 += g_b1[(size_t)bt*128 + gcol + 1];
          v0 = 1.f/(1.f + __expf(-v0));
          v1 = 1.f/(1.f + __expf(-v1));
          if (ct == 0){
            float2 de = *(const float2*)(g_de + off);
            float z0 = v0 * de.x, z1 = v1 * de.y;
            *(float2*)(g_yz + off) = make_float2(z0, z1);
            __nv_bfloat16 h0,l0,h1,l1;
            split_bf16(z0,h0,l0); split_bf16(z1,h1,l1);
            __nv_bfloat162 hv; hv.x=h0; hv.y=h1;
            __nv_bfloat162 lv; lv.x=l0; lv.y=l1;
            *(__nv_bfloat162*)(g_yzh + off) = hv;
            *(__nv_bfloat162*)(g_yzl + off) = lv;
          } else {
            *(float2*)(g_rg + off) = make_float2(v0, v1);
          }
        } else {
          v0 = tanhf(v0 + g_bu[(size_t)bt*64 + gcol]);
          v1 = tanhf(v1 + g_bu[(size_t)bt*64 + gcol + 1]);
          *(float2*)(g_hc + off) = make_float2(v0, v1);
        }
      }
    }
  }
}

// ---------------- 6) final projection ----------------
__global__ void k_out(const float* __restrict__ outw, const float* __restrict__ outb,
                      float* __restrict__ out){
  int gw = blockIdx.x*8 + (threadIdx.x >> 5);
  int lane = threadIdx.x & 31;
  size_t mn = (size_t)gw;
  int m = gw >> 9;
  int t = m % 12;
  size_t base = mn << 6;
  float s = 0.f;
  #pragma unroll
  for (int ii = 0; ii < 2; ii++){
    int i = lane + ii*32;
    float rg = g_rg[base + i];
    float de = g_de[base + i];
    float hc = g_hc[base + i];
    float st = fmaf(rg, de - hc, hc);
    s = fmaf(st, outw[t*64 + i], s);
  }
  #pragma unroll
  for (int off = 16; off > 0; off >>= 1) s += __shfl_xor_sync(0xffffffffu, s, off);
  if (lane == 0) out[mn] = s + outb[t];
}

// ---------------- launch ----------------
extern "C" void kernel_launch(void* const* d_in, const int* in_sizes, int n_in,
                              void* d_out, int out_size){
  (void)in_sizes; (void)n_in; (void)out_size;
  const float* hn  = (const float*)d_in[2];
  const float* ne1 = (const float*)d_in[3];
  const float* ne2 = (const float*)d_in[4];
  const float* E   = (const float*)d_in[5];
  const float* Wq  = (const float*)d_in[6];
  const float* bq  = (const float*)d_in[7];
  const float* Wk  = (const float*)d_in[8];
  const float* bk  = (const float*)d_in[9];
  const float* Wv  = (const float*)d_in[10];
  const float* bv  = (const float*)d_in[11];
  const float* taw = (const float*)d_in[12];
  const float* tab = (const float*)d_in[13];
  const float* gwp = (const float*)d_in[14];
  const float* gw  = (const float*)d_in[15];
  const float* gbp = (const float*)d_in[16];
  const float* gb  = (const float*)d_in[17];
  const float* uwp = (const float*)d_in[18];
  const float* uw  = (const float*)d_in[19];
  const float* ubp = (const float*)d_in[20];
  const float* ub  = (const float*)d_in[21];
  const float* outw= (const float*)d_in[22];
  const float* outb= (const float*)d_in[23];
  float* out = (float*)d_out;

  cudaFuncSetAttribute(k_bmma2, cudaFuncAttributeMaxDynamicSharedMemorySize, SMB);
  cudaFuncSetAttribute(k_qa, cudaFuncAttributeMaxDynamicSharedMemorySize, QA_SMB);

  k_adj<<<512, 512>>>(E);                                          // 1
  k_a2<<<dim3(4, 8), 128>>>();                                     // 2
  k_qa<<<512, 256, QA_SMB>>>(hn, ne1, ne2, Wq, bq, Wk, bk, Wv, bv, taw, tab); // 3
  k_bmma2<<<dim3(4, 768), 256, SMB>>>(0);                          // 4 (profiled)
  k_wgen<<<dim3(390, 12), 256>>>(ne2, gwp, gw, 24960, 0);
  k_wgen<<<dim3(195, 12), 256>>>(ne2, uwp, uw, 12480, 1);
  k_wgen<<<dim3(2, 12), 256>>>(ne2, gbp, gb, 128, 2);
  k_wgen<<<dim3(1, 12), 256>>>(ne2, ubp, ub, 64, 3);
  k_combT<0><<<dim3(2, 4, 768), 256>>>();        // yz / rg
  k_bmma2<<<dim3(4, 768), 256, SMB>>>(1);        // y1 = A@yz, y2 = M2@yz - yz
  k_combT<1><<<dim3(1, 4, 768), 256>>>();        // hc
  k_out<<<49152, 256>>>(outw, outb, out);
}